// round 1
// baseline (speedup 1.0000x reference)
#include <cuda_runtime.h>
#include <cuda_bf16.h>
#include <math.h>

// ---------------------------------------------------------------------------
// ProteinInteractionPredictor:
//   meta branches: 1x1024 -> 256 -> 128 (relu)
//   graph branches: 3x GCNConv(128->128) with relu, then mean-pool over 50000 nodes
//   head: concat[512] -> 256 -> 128 -> 1 -> sigmoid
//
// GCNConv: out = inv_sqrt[i] * ( sum_{e: dst=i} inv_sqrt[src] * h[src]
//                               + inv_sqrt[i] * h[i] ) + b,   h = x @ W
// ---------------------------------------------------------------------------

#define MAXN 50000
#define MAXE 800000
#define F 128
#define PBLK 256   // pooling partial blocks

// scratch (static device globals; no allocation at runtime)
__device__ float g_H[MAXN * F];          // GEMM output (pre-aggregation)
__device__ float g_Y[MAXN * F];          // conv output (post relu)
__device__ int   g_cnt[MAXN];            // in-degree (without self loop)
__device__ int   g_cursor[MAXN];
__device__ int   g_offs[MAXN + 1];       // CSR offsets
__device__ float g_invs[MAXN];           // 1/sqrt(deg+1)
__device__ int   g_csr[MAXE];            // src node per CSR slot
__device__ float g_partial[2 * PBLK * F];// pooling partials for both graphs

// ---------------------------------------------------------------------------
// CSR build
// ---------------------------------------------------------------------------
__global__ void init_kernel(int n) {
    int i = blockIdx.x * blockDim.x + threadIdx.x;
    if (i < n) { g_cnt[i] = 0; g_cursor[i] = 0; }
}

__global__ void count_kernel(const int* __restrict__ dst, int e_cnt) {
    int e = blockIdx.x * blockDim.x + threadIdx.x;
    if (e < e_cnt) atomicAdd(&g_cnt[dst[e]], 1);
}

// single block, 1024 threads: exclusive scan of g_cnt -> g_offs, plus inv_sqrt
__global__ void scan_kernel(int n) {
    __shared__ int ssum[1024];
    int t = threadIdx.x;
    int ch = (n + 1023) / 1024;
    int b = t * ch;
    int e = min(n, b + ch);
    int s = 0;
    for (int i = b; i < e; i++) s += g_cnt[i];
    ssum[t] = s;
    __syncthreads();
    for (int d = 1; d < 1024; d <<= 1) {
        int v = (t >= d) ? ssum[t - d] : 0;
        __syncthreads();
        ssum[t] += v;
        __syncthreads();
    }
    int run = (t > 0) ? ssum[t - 1] : 0;   // exclusive prefix of this chunk
    for (int i = b; i < e; i++) {
        g_offs[i] = run;
        run += g_cnt[i];
        g_invs[i] = rsqrtf((float)(g_cnt[i] + 1));  // +1 self loop; always > 0
    }
    if (t == 1023) g_offs[n] = run;
}

__global__ void fill_kernel(const int* __restrict__ src, const int* __restrict__ dst,
                            int e_cnt) {
    int e = blockIdx.x * blockDim.x + threadIdx.x;
    if (e < e_cnt) {
        int d = dst[e];
        int p = atomicAdd(&g_cursor[d], 1);
        g_csr[g_offs[d] + p] = src[e];
    }
}

// ---------------------------------------------------------------------------
// GEMM: C[M,128] = A[M,128] @ W[128,128]
// BM=64 BN=128 BK=32, 256 threads, each computes 4x8.
// If a_ext == nullptr, A = g_Y (previous conv output).
// ---------------------------------------------------------------------------
#define BM 64
#define BN 128
#define BK 32
#define TM 4
#define TN 8

__global__ __launch_bounds__(256) void gemm_kernel(const float* __restrict__ a_ext,
                                                   const float* __restrict__ W, int M) {
    const float* __restrict__ A = a_ext ? a_ext : g_Y;
    __shared__ float As[BK][BM];    // transposed A tile
    __shared__ float Bs[BK][BN];

    int block_row = blockIdx.x * BM;
    int tid = threadIdx.x;
    int tx = tid & 15;
    int ty = tid >> 4;

    float acc[TM][TN];
#pragma unroll
    for (int i = 0; i < TM; i++)
#pragma unroll
        for (int j = 0; j < TN; j++) acc[i][j] = 0.f;

    for (int k0 = 0; k0 < F; k0 += BK) {
        // A tile: 64 rows x 32 cols = 512 float4 loads, 2 per thread
#pragma unroll
        for (int l = 0; l < 2; l++) {
            int idx = tid + l * 256;          // 0..511
            int m = idx >> 3;                 // row 0..63
            int kq = (idx & 7) * 4;           // col in chunk
            float4 v = make_float4(0.f, 0.f, 0.f, 0.f);
            int gr = block_row + m;
            if (gr < M) v = *reinterpret_cast<const float4*>(A + gr * F + k0 + kq);
            As[kq + 0][m] = v.x; As[kq + 1][m] = v.y;
            As[kq + 2][m] = v.z; As[kq + 3][m] = v.w;
        }
        // B tile: 32 rows x 128 cols = 1024 float4, 4 per thread
#pragma unroll
        for (int l = 0; l < 4; l++) {
            int idx = tid + l * 256;          // 0..1023
            int kr = idx >> 5;                // 0..31
            int nq = (idx & 31) * 4;
            *reinterpret_cast<float4*>(&Bs[kr][nq]) =
                *reinterpret_cast<const float4*>(W + (k0 + kr) * F + nq);
        }
        __syncthreads();

#pragma unroll
        for (int k = 0; k < BK; k++) {
            float4 a4 = *reinterpret_cast<const float4*>(&As[k][ty * TM]);
            float4 b0 = *reinterpret_cast<const float4*>(&Bs[k][tx * TN]);
            float4 b1 = *reinterpret_cast<const float4*>(&Bs[k][tx * TN + 4]);
            float a[TM] = {a4.x, a4.y, a4.z, a4.w};
            float b[TN] = {b0.x, b0.y, b0.z, b0.w, b1.x, b1.y, b1.z, b1.w};
#pragma unroll
            for (int i = 0; i < TM; i++)
#pragma unroll
                for (int j = 0; j < TN; j++) acc[i][j] += a[i] * b[j];
        }
        __syncthreads();
    }

#pragma unroll
    for (int i = 0; i < TM; i++) {
        int gr = block_row + ty * TM + i;
        if (gr < M) {
#pragma unroll
            for (int j = 0; j < TN; j += 4) {
                float4 v = make_float4(acc[i][j], acc[i][j + 1], acc[i][j + 2], acc[i][j + 3]);
                *reinterpret_cast<float4*>(g_H + gr * F + tx * TN + j) = v;
            }
        }
    }
}

// ---------------------------------------------------------------------------
// Aggregation: one block per node, 128 threads = 128 columns.
// Y[i] = relu( inv[i] * ( sum_e inv[src_e]*H[src_e] + inv[i]*H[i] ) + b )
// ---------------------------------------------------------------------------
__global__ __launch_bounds__(F) void agg_kernel(const float* __restrict__ bias) {
    int i = blockIdx.x;
    int j = threadIdx.x;
    int beg = g_offs[i];
    int end = g_offs[i + 1];
    float inv_i = g_invs[i];
    float acc = inv_i * g_H[i * F + j];   // self loop contribution

    __shared__ int   s_src[F];
    __shared__ float s_w[F];

    for (int base = beg; base < end; base += F) {
        int cnt = min(F, end - base);
        __syncthreads();
        if (j < cnt) {
            int s = g_csr[base + j];
            s_src[j] = s;
            s_w[j] = g_invs[s];
        }
        __syncthreads();
        for (int t = 0; t < cnt; t++)
            acc += s_w[t] * g_H[s_src[t] * F + j];
    }
    float v = inv_i * acc + bias[j];
    g_Y[i * F + j] = fmaxf(v, 0.f);
}

// ---------------------------------------------------------------------------
// Pooling (phase 1): PBLK blocks x 128 threads; partial column sums of g_Y.
// ---------------------------------------------------------------------------
__global__ __launch_bounds__(F) void pool_partial_kernel(int n, int gslot) {
    int j = threadIdx.x;
    float acc = 0.f;
    for (int i = blockIdx.x; i < n; i += gridDim.x)
        acc += g_Y[i * F + j];
    g_partial[(gslot * PBLK + blockIdx.x) * F + j] = acc;
}

// ---------------------------------------------------------------------------
// Tail: pooling finish + meta branches + head, one block of 256 threads.
// concat order: [ma2(128), mb2(128), ga(128), gb(128)]
// ---------------------------------------------------------------------------
__global__ __launch_bounds__(256) void tail_kernel(
    const float* __restrict__ ma, const float* __restrict__ mb,
    const float* __restrict__ fc1w, const float* __restrict__ fc1b,
    const float* __restrict__ fc2w, const float* __restrict__ fc2b,
    const float* __restrict__ fccw, const float* __restrict__ fccb,
    const float* __restrict__ fcc2w, const float* __restrict__ fcc2b,
    const float* __restrict__ outw, const float* __restrict__ outb,
    float invN, float* __restrict__ out)
{
    __shared__ float s1a[256], s1b[256], c[512], c1[256], c2[128];
    int t = threadIdx.x;

    // finish pooling
    if (t < 128) {
        float sa = 0.f, sb = 0.f;
        for (int p = 0; p < PBLK; p++) {
            sa += g_partial[p * F + t];
            sb += g_partial[(PBLK + p) * F + t];
        }
        c[256 + t] = sa * invN;
        c[384 + t] = sb * invN;
    }
    // meta fc1 (256 outputs, both branches)
    {
        float accA = 0.f, accB = 0.f;
        for (int k = 0; k < 1024; k++) {
            float w = fc1w[k * 256 + t];
            accA += ma[k] * w;
            accB += mb[k] * w;
        }
        s1a[t] = fmaxf(accA + fc1b[t], 0.f);
        s1b[t] = fmaxf(accB + fc1b[t], 0.f);
    }
    __syncthreads();
    // meta fc2 (128 outputs)
    if (t < 128) {
        float accA = 0.f, accB = 0.f;
        for (int k = 0; k < 256; k++) {
            float w = fc2w[k * 128 + t];
            accA += s1a[k] * w;
            accB += s1b[k] * w;
        }
        c[t]       = fmaxf(accA + fc2b[t], 0.f);
        c[128 + t] = fmaxf(accB + fc2b[t], 0.f);
    }
    __syncthreads();
    // fcc: 512 -> 256
    {
        float acc = 0.f;
        for (int k = 0; k < 512; k++) acc += c[k] * fccw[k * 256 + t];
        c1[t] = fmaxf(acc + fccb[t], 0.f);
    }
    __syncthreads();
    // fcc2: 256 -> 128
    if (t < 128) {
        float acc = 0.f;
        for (int k = 0; k < 256; k++) acc += c1[k] * fcc2w[k * 128 + t];
        c2[t] = fmaxf(acc + fcc2b[t], 0.f);
    }
    __syncthreads();
    if (t == 0) {
        float s = 0.f;
        for (int k = 0; k < 128; k++) s += c2[k] * outw[k];
        s += outb[0];
        out[0] = 1.f / (1.f + expf(-s));
    }
}

// ---------------------------------------------------------------------------
// Launch
// ---------------------------------------------------------------------------
extern "C" void kernel_launch(void* const* d_in, const int* in_sizes, int n_in,
                              void* d_out, int out_size) {
    const float* meta_a = (const float*)d_in[0];
    const float* meta_b = (const float*)d_in[1];
    const float* x_a    = (const float*)d_in[2];
    const int*   ei_a   = (const int*)  d_in[3];
    const float* x_b    = (const float*)d_in[4];
    const int*   ei_b   = (const int*)  d_in[5];
    const float* fc1w   = (const float*)d_in[6];
    const float* fc1b   = (const float*)d_in[7];
    const float* fc2w   = (const float*)d_in[8];
    const float* fc2b   = (const float*)d_in[9];
    const float* gcn1w  = (const float*)d_in[10];
    const float* gcn1b  = (const float*)d_in[11];
    const float* gcn2w  = (const float*)d_in[12];
    const float* gcn2b  = (const float*)d_in[13];
    const float* fccw   = (const float*)d_in[14];
    const float* fccb   = (const float*)d_in[15];
    const float* fcc2w  = (const float*)d_in[16];
    const float* fcc2b  = (const float*)d_in[17];
    const float* outw   = (const float*)d_in[18];
    const float* outb   = (const float*)d_in[19];

    int N = in_sizes[2] / F;      // 50000
    int E = in_sizes[3] / 2;      // 800000

    int nb_nodes = (N + 255) / 256;
    int nb_edges = (E + 255) / 256;
    int nb_gemm  = (N + BM - 1) / BM;
    float invN = 1.0f / (float)N;

    for (int g = 0; g < 2; g++) {
        const float* x   = g ? x_b : x_a;
        const int*   src = g ? ei_b : ei_a;
        const int*   dst = src + E;

        init_kernel<<<nb_nodes, 256>>>(N);
        count_kernel<<<nb_edges, 256>>>(dst, E);
        scan_kernel<<<1, 1024>>>(N);
        fill_kernel<<<nb_edges, 256>>>(src, dst, E);

        // conv1: h = x @ gcn1w ; y = relu(agg(h) + gcn1b)
        gemm_kernel<<<nb_gemm, 256>>>(x, gcn1w, N);
        agg_kernel<<<N, F>>>(gcn1b);
        // conv2: input g_Y
        gemm_kernel<<<nb_gemm, 256>>>(nullptr, gcn2w, N);
        agg_kernel<<<N, F>>>(gcn2b);
        // conv3
        gemm_kernel<<<nb_gemm, 256>>>(nullptr, gcn2w, N);
        agg_kernel<<<N, F>>>(gcn2b);

        pool_partial_kernel<<<PBLK, F>>>(N, g);
    }

    tail_kernel<<<1, 256>>>(meta_a, meta_b, fc1w, fc1b, fc2w, fc2b,
                            fccw, fccb, fcc2w, fcc2b, outw, outb,
                            invN, (float*)d_out);
}

// round 2
// speedup vs baseline: 1.1251x; 1.1251x over previous
#include <cuda_runtime.h>
#include <cuda_bf16.h>
#include <math.h>

// ---------------------------------------------------------------------------
// ProteinInteractionPredictor
// GCNConv: Y = relu( Agg(X) @ W + b ), Agg = D^-1/2 (A+I) D^-1/2  (linear, so
// it commutes with the right-multiply by W).
// ---------------------------------------------------------------------------

#define MAXN 50000
#define MAXE 800000
#define F 128
#define PBLK 256

__device__ float g_P[MAXN * F];          // aggregated features (GEMM input)
__device__ float g_Y[MAXN * F];          // conv output (post bias+relu)
__device__ int   g_cnt[MAXN];
__device__ int   g_cursor[MAXN];
__device__ int   g_offs[MAXN + 1];
__device__ float g_invs[MAXN];
__device__ int   g_csr[MAXE];
__device__ float g_partial[2 * PBLK * F];

// ---------------------------------------------------------------------------
// CSR build
// ---------------------------------------------------------------------------
__global__ void init_kernel(int n) {
    int i = blockIdx.x * blockDim.x + threadIdx.x;
    if (i < n) { g_cnt[i] = 0; g_cursor[i] = 0; }
}

__global__ void count_kernel(const int* __restrict__ dst, int e_cnt) {
    int e = blockIdx.x * blockDim.x + threadIdx.x;
    if (e < e_cnt) atomicAdd(&g_cnt[dst[e]], 1);
}

__global__ void scan_kernel(int n) {
    __shared__ int ssum[1024];
    int t = threadIdx.x;
    int ch = (n + 1023) / 1024;
    int b = t * ch;
    int e = min(n, b + ch);
    int s = 0;
    for (int i = b; i < e; i++) s += g_cnt[i];
    ssum[t] = s;
    __syncthreads();
    for (int d = 1; d < 1024; d <<= 1) {
        int v = (t >= d) ? ssum[t - d] : 0;
        __syncthreads();
        ssum[t] += v;
        __syncthreads();
    }
    int run = (t > 0) ? ssum[t - 1] : 0;
    for (int i = b; i < e; i++) {
        g_offs[i] = run;
        run += g_cnt[i];
        g_invs[i] = rsqrtf((float)(g_cnt[i] + 1));
    }
    if (t == 1023) g_offs[n] = run;
}

__global__ void fill_kernel(const int* __restrict__ src, const int* __restrict__ dst,
                            int e_cnt) {
    int e = blockIdx.x * blockDim.x + threadIdx.x;
    if (e < e_cnt) {
        int d = dst[e];
        int p = atomicAdd(&g_cursor[d], 1);
        g_csr[g_offs[d] + p] = src[e];
    }
}

// ---------------------------------------------------------------------------
// Aggregation (pure linear): P[i] = inv[i]*( sum_e inv[src]*X[src] + inv[i]*X[i] )
// one block per node, 128 threads = 128 columns. X = x_ext or g_Y.
// ---------------------------------------------------------------------------
__global__ __launch_bounds__(F) void agg_kernel(const float* __restrict__ x_ext) {
    const float* __restrict__ X = x_ext ? x_ext : g_Y;
    int i = blockIdx.x;
    int j = threadIdx.x;
    int beg = g_offs[i];
    int end = g_offs[i + 1];
    float inv_i = g_invs[i];
    float acc = inv_i * X[i * F + j];

    __shared__ int   s_src[F];
    __shared__ float s_w[F];

    for (int base = beg; base < end; base += F) {
        int cnt = min(F, end - base);
        __syncthreads();
        if (j < cnt) {
            int s = g_csr[base + j];
            s_src[j] = s;
            s_w[j] = g_invs[s];
        }
        __syncthreads();
        for (int t = 0; t < cnt; t++)
            acc += s_w[t] * X[s_src[t] * F + j];
    }
    g_P[i * F + j] = inv_i * acc;
}

// ---------------------------------------------------------------------------
// GEMM + bias + relu: g_Y[M,128] = relu( g_P @ W + b )
// W (128x128, 64KB) resident in smem for the whole block. BM=128 rows/block.
// 256 threads = (tx 0..31) x (ty 0..7); thread tile 16 rows x 4 cols (float4).
// Dynamic smem: Ws[128*128] + As[32*128] = 80KB.
// ---------------------------------------------------------------------------
#define GBM 128
#define GBK 32
#define GEMM_SMEM ((F * F + GBK * GBM) * 4)

__global__ __launch_bounds__(256) void gemm_kernel(const float* __restrict__ W,
                                                   const float* __restrict__ bias,
                                                   int M) {
    extern __shared__ float sm[];
    float* Ws = sm;             // [128][128]
    float* As = sm + F * F;     // [GBK][GBM]

    const float* __restrict__ A = g_P;
    int tid = threadIdx.x;
    int tx = tid & 31;
    int ty = tid >> 5;
    int tx4 = tx * 4;
    int ty16 = ty * 16;
    int row0 = blockIdx.x * GBM;

    // Load full W into smem (coalesced, conflict-free)
#pragma unroll
    for (int l = 0; l < 16; l++) {
        int idx = tid + l * 256;          // 0..4095 float4s
        int k = idx >> 5;
        int n4 = (idx & 31) * 4;
        *reinterpret_cast<float4*>(&Ws[k * F + n4]) =
            *reinterpret_cast<const float4*>(W + k * F + n4);
    }

    float acc[16][4];
#pragma unroll
    for (int i = 0; i < 16; i++)
#pragma unroll
        for (int j = 0; j < 4; j++) acc[i][j] = 0.f;

    for (int k0 = 0; k0 < F; k0 += GBK) {
        // A tile: 128 rows x 32 k. m-major indexing so smem stores are
        // conflict-free (bank = m % 32, all lanes distinct).
#pragma unroll
        for (int l = 0; l < 4; l++) {
            int idx = tid + l * 256;      // 0..1023
            int m = idx & 127;
            int kc = idx >> 7;            // 0..7
            float4 v = make_float4(0.f, 0.f, 0.f, 0.f);
            int gr = row0 + m;
            if (gr < M)
                v = *reinterpret_cast<const float4*>(A + gr * F + k0 + kc * 4);
            As[(kc * 4 + 0) * GBM + m] = v.x;
            As[(kc * 4 + 1) * GBM + m] = v.y;
            As[(kc * 4 + 2) * GBM + m] = v.z;
            As[(kc * 4 + 3) * GBM + m] = v.w;
        }
        __syncthreads();

#pragma unroll 8
        for (int k = 0; k < GBK; k++) {
            float4 b = *reinterpret_cast<const float4*>(&Ws[(k0 + k) * F + tx4]);
            const float* arow = &As[k * GBM + ty16];
#pragma unroll
            for (int i = 0; i < 16; i++) {
                float a = arow[i];        // broadcast (ty uniform per warp)
                acc[i][0] += a * b.x;
                acc[i][1] += a * b.y;
                acc[i][2] += a * b.z;
                acc[i][3] += a * b.w;
            }
        }
        __syncthreads();
    }

    float4 bv = *reinterpret_cast<const float4*>(bias + tx4);
#pragma unroll
    for (int i = 0; i < 16; i++) {
        int gr = row0 + ty16 + i;
        if (gr < M) {
            float4 o;
            o.x = fmaxf(acc[i][0] + bv.x, 0.f);
            o.y = fmaxf(acc[i][1] + bv.y, 0.f);
            o.z = fmaxf(acc[i][2] + bv.z, 0.f);
            o.w = fmaxf(acc[i][3] + bv.w, 0.f);
            *reinterpret_cast<float4*>(g_Y + gr * F + tx4) = o;
        }
    }
}

// ---------------------------------------------------------------------------
// Pooling partials over g_Y
// ---------------------------------------------------------------------------
__global__ __launch_bounds__(F) void pool_partial_kernel(int n, int gslot) {
    int j = threadIdx.x;
    float acc = 0.f;
    for (int i = blockIdx.x; i < n; i += gridDim.x)
        acc += g_Y[i * F + j];
    g_partial[(gslot * PBLK + blockIdx.x) * F + j] = acc;
}

// ---------------------------------------------------------------------------
// Tail: pooling finish + meta branches + head
// ---------------------------------------------------------------------------
__global__ __launch_bounds__(256) void tail_kernel(
    const float* __restrict__ ma, const float* __restrict__ mb,
    const float* __restrict__ fc1w, const float* __restrict__ fc1b,
    const float* __restrict__ fc2w, const float* __restrict__ fc2b,
    const float* __restrict__ fccw, const float* __restrict__ fccb,
    const float* __restrict__ fcc2w, const float* __restrict__ fcc2b,
    const float* __restrict__ outw, const float* __restrict__ outb,
    float invN, float* __restrict__ out)
{
    __shared__ float s1a[256], s1b[256], c[512], c1[256], c2[128];
    int t = threadIdx.x;

    if (t < 128) {
        float sa = 0.f, sb = 0.f;
        for (int p = 0; p < PBLK; p++) {
            sa += g_partial[p * F + t];
            sb += g_partial[(PBLK + p) * F + t];
        }
        c[256 + t] = sa * invN;
        c[384 + t] = sb * invN;
    }
    {
        float accA = 0.f, accB = 0.f;
        for (int k = 0; k < 1024; k++) {
            float w = fc1w[k * 256 + t];
            accA += ma[k] * w;
            accB += mb[k] * w;
        }
        s1a[t] = fmaxf(accA + fc1b[t], 0.f);
        s1b[t] = fmaxf(accB + fc1b[t], 0.f);
    }
    __syncthreads();
    if (t < 128) {
        float accA = 0.f, accB = 0.f;
        for (int k = 0; k < 256; k++) {
            float w = fc2w[k * 128 + t];
            accA += s1a[k] * w;
            accB += s1b[k] * w;
        }
        c[t]       = fmaxf(accA + fc2b[t], 0.f);
        c[128 + t] = fmaxf(accB + fc2b[t], 0.f);
    }
    __syncthreads();
    {
        float acc = 0.f;
        for (int k = 0; k < 512; k++) acc += c[k] * fccw[k * 256 + t];
        c1[t] = fmaxf(acc + fccb[t], 0.f);
    }
    __syncthreads();
    if (t < 128) {
        float acc = 0.f;
        for (int k = 0; k < 256; k++) acc += c1[k] * fcc2w[k * 128 + t];
        c2[t] = fmaxf(acc + fcc2b[t], 0.f);
    }
    __syncthreads();
    if (t == 0) {
        float s = 0.f;
        for (int k = 0; k < 128; k++) s += c2[k] * outw[k];
        s += outb[0];
        out[0] = 1.f / (1.f + expf(-s));
    }
}

// ---------------------------------------------------------------------------
// Launch
// ---------------------------------------------------------------------------
extern "C" void kernel_launch(void* const* d_in, const int* in_sizes, int n_in,
                              void* d_out, int out_size) {
    const float* meta_a = (const float*)d_in[0];
    const float* meta_b = (const float*)d_in[1];
    const float* x_a    = (const float*)d_in[2];
    const int*   ei_a   = (const int*)  d_in[3];
    const float* x_b    = (const float*)d_in[4];
    const int*   ei_b   = (const int*)  d_in[5];
    const float* fc1w   = (const float*)d_in[6];
    const float* fc1b   = (const float*)d_in[7];
    const float* fc2w   = (const float*)d_in[8];
    const float* fc2b   = (const float*)d_in[9];
    const float* gcn1w  = (const float*)d_in[10];
    const float* gcn1b  = (const float*)d_in[11];
    const float* gcn2w  = (const float*)d_in[12];
    const float* gcn2b  = (const float*)d_in[13];
    const float* fccw   = (const float*)d_in[14];
    const float* fccb   = (const float*)d_in[15];
    const float* fcc2w  = (const float*)d_in[16];
    const float* fcc2b  = (const float*)d_in[17];
    const float* outw   = (const float*)d_in[18];
    const float* outb   = (const float*)d_in[19];

    int N = in_sizes[2] / F;
    int E = in_sizes[3] / 2;

    int nb_nodes = (N + 255) / 256;
    int nb_edges = (E + 255) / 256;
    int nb_gemm  = (N + GBM - 1) / GBM;
    float invN = 1.0f / (float)N;

    static bool attr_set = false;
    if (!attr_set) {
        cudaFuncSetAttribute(gemm_kernel,
                             cudaFuncAttributeMaxDynamicSharedMemorySize, GEMM_SMEM);
        attr_set = true;
    }

    for (int g = 0; g < 2; g++) {
        const float* x   = g ? x_b : x_a;
        const int*   src = g ? ei_b : ei_a;
        const int*   dst = src + E;

        init_kernel<<<nb_nodes, 256>>>(N);
        count_kernel<<<nb_edges, 256>>>(dst, E);
        scan_kernel<<<1, 1024>>>(N);
        fill_kernel<<<nb_edges, 256>>>(src, dst, E);

        // conv1
        agg_kernel<<<N, F>>>(x);
        gemm_kernel<<<nb_gemm, 256, GEMM_SMEM>>>(gcn1w, gcn1b, N);
        // conv2
        agg_kernel<<<N, F>>>(nullptr);
        gemm_kernel<<<nb_gemm, 256, GEMM_SMEM>>>(gcn2w, gcn2b, N);
        // conv3
        agg_kernel<<<N, F>>>(nullptr);
        gemm_kernel<<<nb_gemm, 256, GEMM_SMEM>>>(gcn2w, gcn2b, N);

        pool_partial_kernel<<<PBLK, F>>>(N, g);
    }

    tail_kernel<<<1, 256>>>(meta_a, meta_b, fc1w, fc1b, fc2w, fc2b,
                            fccw, fccb, fcc2w, fcc2b, outw, outb,
                            invN, (float*)d_out);
}

// round 3
// speedup vs baseline: 1.5831x; 1.4071x over previous
#include <cuda_runtime.h>
#include <cuda_bf16.h>
#include <math.h>

// ---------------------------------------------------------------------------
// ProteinInteractionPredictor. GCNConv: Y = relu( Agg(X) @ W + b ).
// Graph A on legacy stream, graph B + meta branch on side streams (fork-join
// with events -> parallel branches in the captured graph).
// ---------------------------------------------------------------------------

#define MAXN 50000
#define MAXE 800000
#define F 128
#define PBLK 256

// per-graph scratch banks
__device__ float g_PA[MAXN * F];
__device__ float g_YA[MAXN * F];
__device__ float g_PB[MAXN * F];
__device__ float g_YB[MAXN * F];
__device__ int   g_cntA[MAXN],    g_cntB[MAXN];
__device__ int   g_cursorA[MAXN], g_cursorB[MAXN];
__device__ int   g_offsA[MAXN + 1], g_offsB[MAXN + 1];
__device__ float g_invsA[MAXN],   g_invsB[MAXN];
__device__ int   g_csrA[MAXE],    g_csrB[MAXE];
__device__ float g_partial[2 * PBLK * F];
__device__ float g_meta[256];

// ---------------------------------------------------------------------------
// f32x2 helpers
// ---------------------------------------------------------------------------
__device__ __forceinline__ void ffma2(unsigned long long& d,
                                      unsigned long long a, unsigned long long b) {
    asm("fma.rn.f32x2 %0, %1, %2, %0;" : "+l"(d) : "l"(a), "l"(b));
}
__device__ __forceinline__ unsigned long long pack2(float x, float y) {
    unsigned long long r;
    asm("mov.b64 %0, {%1, %2};" : "=l"(r) : "f"(x), "f"(y));
    return r;
}
__device__ __forceinline__ float f2lo(unsigned long long v) {
    return __uint_as_float((unsigned)v);
}
__device__ __forceinline__ float f2hi(unsigned long long v) {
    return __uint_as_float((unsigned)(v >> 32));
}

// ---------------------------------------------------------------------------
// CSR build (per graph bank gb)
// ---------------------------------------------------------------------------
__global__ void init_kernel(int n, int gb) {
    int* cnt = gb ? g_cntB : g_cntA;
    int* cur = gb ? g_cursorB : g_cursorA;
    int i = blockIdx.x * blockDim.x + threadIdx.x;
    if (i < n) { cnt[i] = 0; cur[i] = 0; }
}

__global__ void count_kernel(const int* __restrict__ dst, int e_cnt, int gb) {
    int* cnt = gb ? g_cntB : g_cntA;
    int e = blockIdx.x * blockDim.x + threadIdx.x;
    if (e < e_cnt) atomicAdd(&cnt[dst[e]], 1);
}

__global__ void scan_kernel(int n, int gb) {
    int*   cnt  = gb ? g_cntB : g_cntA;
    int*   offs = gb ? g_offsB : g_offsA;
    float* invs = gb ? g_invsB : g_invsA;
    __shared__ int ssum[1024];
    int t = threadIdx.x;
    int ch = (n + 1023) / 1024;
    int b = t * ch;
    int e = min(n, b + ch);
    int s = 0;
    for (int i = b; i < e; i++) s += cnt[i];
    ssum[t] = s;
    __syncthreads();
    for (int d = 1; d < 1024; d <<= 1) {
        int v = (t >= d) ? ssum[t - d] : 0;
        __syncthreads();
        ssum[t] += v;
        __syncthreads();
    }
    int run = (t > 0) ? ssum[t - 1] : 0;
    for (int i = b; i < e; i++) {
        offs[i] = run;
        run += cnt[i];
        invs[i] = rsqrtf((float)(cnt[i] + 1));
    }
    if (t == 1023) offs[n] = run;
}

__global__ void fill_kernel(const int* __restrict__ src, const int* __restrict__ dst,
                            int e_cnt, int gb) {
    int* cur  = gb ? g_cursorB : g_cursorA;
    int* offs = gb ? g_offsB : g_offsA;
    int* csr  = gb ? g_csrB : g_csrA;
    int e = blockIdx.x * blockDim.x + threadIdx.x;
    if (e < e_cnt) {
        int d = dst[e];
        int p = atomicAdd(&cur[d], 1);
        csr[offs[d] + p] = src[e];
    }
}

// ---------------------------------------------------------------------------
// Aggregation: P[i] = inv[i]*( sum_e inv[src]*X[src] + inv[i]*X[i] )
// ---------------------------------------------------------------------------
__global__ __launch_bounds__(F) void agg_kernel(const float* __restrict__ x_ext, int gb) {
    const int*   offs = gb ? g_offsB : g_offsA;
    const float* invs = gb ? g_invsB : g_invsA;
    const int*   csr  = gb ? g_csrB : g_csrA;
    float*       P    = gb ? g_PB : g_PA;
    const float* __restrict__ X = x_ext ? x_ext : (gb ? g_YB : g_YA);

    int i = blockIdx.x;
    int j = threadIdx.x;
    int beg = offs[i];
    int end = offs[i + 1];
    float inv_i = invs[i];
    float acc = inv_i * X[i * F + j];

    __shared__ int   s_src[F];
    __shared__ float s_w[F];

    for (int base = beg; base < end; base += F) {
        int cnt = min(F, end - base);
        __syncthreads();
        if (j < cnt) {
            int s = csr[base + j];
            s_src[j] = s;
            s_w[j] = invs[s];
        }
        __syncthreads();
#pragma unroll 4
        for (int t = 0; t < cnt; t++)
            acc += s_w[t] * X[s_src[t] * F + j];
    }
    P[i * F + j] = inv_i * acc;
}

// ---------------------------------------------------------------------------
// GEMM + bias + relu via packed f32x2 FMA. Y = relu(P @ W + b).
// W full in smem; A tile [GBK k][128 m] transposed, stride 130.
// 256 thr = 32 tx (4 cols each) x 8 ty (16 rows each, as 8 row-pairs).
// ---------------------------------------------------------------------------
#define GBM 128
#define GBK 32
#define ASTRIDE 130
#define GEMM_SMEM ((F * F + GBK * ASTRIDE) * 4)

__global__ __launch_bounds__(256) void gemm_kernel(const float* __restrict__ W,
                                                   const float* __restrict__ bias,
                                                   int M, int gb) {
    extern __shared__ float sm[];
    float* Ws = sm;                 // [128][128]
    float* As = sm + F * F;         // [GBK][ASTRIDE]

    const float* __restrict__ A = gb ? g_PB : g_PA;
    float* __restrict__ Y = gb ? g_YB : g_YA;

    int tid = threadIdx.x;
    int tx = tid & 31;
    int ty = tid >> 5;
    int tx4 = tx * 4;
    int ty16 = ty * 16;
    int row0 = blockIdx.x * GBM;

#pragma unroll
    for (int l = 0; l < 16; l++) {
        int idx = tid + l * 256;
        int k = idx >> 5;
        int n4 = (idx & 31) * 4;
        *reinterpret_cast<float4*>(&Ws[k * F + n4]) =
            *reinterpret_cast<const float4*>(W + k * F + n4);
    }

    unsigned long long acc[8][4];
#pragma unroll
    for (int p = 0; p < 8; p++)
#pragma unroll
        for (int j = 0; j < 4; j++) acc[p][j] = 0ULL;

    for (int k0 = 0; k0 < F; k0 += GBK) {
        // A tile load: lanes sweep k fastest -> coalesced 128B global reads.
#pragma unroll
        for (int l = 0; l < 4; l++) {
            int idx = tid + l * 256;        // 0..1023
            int m = idx >> 3;               // 0..127
            int kc = idx & 7;               // 0..7 (float4 within 32-k chunk)
            float4 v = make_float4(0.f, 0.f, 0.f, 0.f);
            int gr = row0 + m;
            if (gr < M)
                v = *reinterpret_cast<const float4*>(A + gr * F + k0 + kc * 4);
            As[(kc * 4 + 0) * ASTRIDE + m] = v.x;
            As[(kc * 4 + 1) * ASTRIDE + m] = v.y;
            As[(kc * 4 + 2) * ASTRIDE + m] = v.z;
            As[(kc * 4 + 3) * ASTRIDE + m] = v.w;
        }
        __syncthreads();

#pragma unroll 8
        for (int k = 0; k < GBK; k++) {
            float4 b = *reinterpret_cast<const float4*>(&Ws[(k0 + k) * F + tx4]);
            unsigned long long bx = pack2(b.x, b.x);
            unsigned long long by = pack2(b.y, b.y);
            unsigned long long bz = pack2(b.z, b.z);
            unsigned long long bw = pack2(b.w, b.w);
            const unsigned long long* ar =
                reinterpret_cast<const unsigned long long*>(&As[k * ASTRIDE + ty16]);
#pragma unroll
            for (int p = 0; p < 8; p++) {
                unsigned long long a2 = ar[p];   // rows (ty16+2p, ty16+2p+1), broadcast
                ffma2(acc[p][0], a2, bx);
                ffma2(acc[p][1], a2, by);
                ffma2(acc[p][2], a2, bz);
                ffma2(acc[p][3], a2, bw);
            }
        }
        __syncthreads();
    }

    float4 bv = *reinterpret_cast<const float4*>(bias + tx4);
#pragma unroll
    for (int p = 0; p < 8; p++) {
        int gr = row0 + ty16 + 2 * p;
        if (gr < M) {
            float4 o;
            o.x = fmaxf(f2lo(acc[p][0]) + bv.x, 0.f);
            o.y = fmaxf(f2lo(acc[p][1]) + bv.y, 0.f);
            o.z = fmaxf(f2lo(acc[p][2]) + bv.z, 0.f);
            o.w = fmaxf(f2lo(acc[p][3]) + bv.w, 0.f);
            *reinterpret_cast<float4*>(Y + gr * F + tx4) = o;
        }
        if (gr + 1 < M) {
            float4 o;
            o.x = fmaxf(f2hi(acc[p][0]) + bv.x, 0.f);
            o.y = fmaxf(f2hi(acc[p][1]) + bv.y, 0.f);
            o.z = fmaxf(f2hi(acc[p][2]) + bv.z, 0.f);
            o.w = fmaxf(f2hi(acc[p][3]) + bv.w, 0.f);
            *reinterpret_cast<float4*>(Y + (gr + 1) * F + tx4) = o;
        }
    }
}

// ---------------------------------------------------------------------------
// Pooling partials
// ---------------------------------------------------------------------------
__global__ __launch_bounds__(F) void pool_partial_kernel(int n, int gb) {
    const float* Y = gb ? g_YB : g_YA;
    int j = threadIdx.x;
    float acc = 0.f;
    for (int i = blockIdx.x; i < n; i += gridDim.x)
        acc += Y[i * F + j];
    g_partial[(gb * PBLK + blockIdx.x) * F + j] = acc;
}

// ---------------------------------------------------------------------------
// Meta branch (both inputs): 1024 -> 256 relu -> 128 relu. Writes g_meta[256].
// ---------------------------------------------------------------------------
__global__ __launch_bounds__(256) void meta_kernel(
    const float* __restrict__ ma, const float* __restrict__ mb,
    const float* __restrict__ fc1w, const float* __restrict__ fc1b,
    const float* __restrict__ fc2w, const float* __restrict__ fc2b)
{
    __shared__ float s1a[256], s1b[256];
    int t = threadIdx.x;
    float accA = 0.f, accB = 0.f;
    for (int k = 0; k < 1024; k++) {
        float w = fc1w[k * 256 + t];
        accA += ma[k] * w;
        accB += mb[k] * w;
    }
    s1a[t] = fmaxf(accA + fc1b[t], 0.f);
    s1b[t] = fmaxf(accB + fc1b[t], 0.f);
    __syncthreads();
    if (t < 128) {
        float oA = 0.f, oB = 0.f;
        for (int k = 0; k < 256; k++) {
            float w = fc2w[k * 128 + t];
            oA += s1a[k] * w;
            oB += s1b[k] * w;
        }
        g_meta[t]       = fmaxf(oA + fc2b[t], 0.f);
        g_meta[128 + t] = fmaxf(oB + fc2b[t], 0.f);
    }
}

// ---------------------------------------------------------------------------
// Tail: pool finish + head
// ---------------------------------------------------------------------------
__global__ __launch_bounds__(256) void tail_kernel(
    const float* __restrict__ fccw, const float* __restrict__ fccb,
    const float* __restrict__ fcc2w, const float* __restrict__ fcc2b,
    const float* __restrict__ outw, const float* __restrict__ outb,
    float invN, float* __restrict__ out)
{
    __shared__ float c[512], c1[256], c2[128];
    int t = threadIdx.x;

    if (t < 128) {
        float sa = 0.f, sb = 0.f;
        for (int p = 0; p < PBLK; p++) {
            sa += g_partial[p * F + t];
            sb += g_partial[(PBLK + p) * F + t];
        }
        c[256 + t] = sa * invN;
        c[384 + t] = sb * invN;
        c[t]       = g_meta[t];
        c[128 + t] = g_meta[128 + t];
    }
    __syncthreads();
    {
        float acc = 0.f;
        for (int k = 0; k < 512; k++) acc += c[k] * fccw[k * 256 + t];
        c1[t] = fmaxf(acc + fccb[t], 0.f);
    }
    __syncthreads();
    if (t < 128) {
        float acc = 0.f;
        for (int k = 0; k < 256; k++) acc += c1[k] * fcc2w[k * 128 + t];
        c2[t] = fmaxf(acc + fcc2b[t], 0.f);
    }
    __syncthreads();
    if (t == 0) {
        float s = 0.f;
        for (int k = 0; k < 128; k++) s += c2[k] * outw[k];
        s += outb[0];
        out[0] = 1.f / (1.f + expf(-s));
    }
}

// ---------------------------------------------------------------------------
// Launch
// ---------------------------------------------------------------------------
extern "C" void kernel_launch(void* const* d_in, const int* in_sizes, int n_in,
                              void* d_out, int out_size) {
    const float* meta_a = (const float*)d_in[0];
    const float* meta_b = (const float*)d_in[1];
    const float* x_a    = (const float*)d_in[2];
    const int*   ei_a   = (const int*)  d_in[3];
    const float* x_b    = (const float*)d_in[4];
    const int*   ei_b   = (const int*)  d_in[5];
    const float* fc1w   = (const float*)d_in[6];
    const float* fc1b   = (const float*)d_in[7];
    const float* fc2w   = (const float*)d_in[8];
    const float* fc2b   = (const float*)d_in[9];
    const float* gcn1w  = (const float*)d_in[10];
    const float* gcn1b  = (const float*)d_in[11];
    const float* gcn2w  = (const float*)d_in[12];
    const float* gcn2b  = (const float*)d_in[13];
    const float* fccw   = (const float*)d_in[14];
    const float* fccb   = (const float*)d_in[15];
    const float* fcc2w  = (const float*)d_in[16];
    const float* fcc2b  = (const float*)d_in[17];
    const float* outw   = (const float*)d_in[18];
    const float* outb   = (const float*)d_in[19];

    int N = in_sizes[2] / F;
    int E = in_sizes[3] / 2;

    int nb_nodes = (N + 255) / 256;
    int nb_edges = (E + 255) / 256;
    int nb_gemm  = (N + GBM - 1) / GBM;
    float invN = 1.0f / (float)N;

    static cudaStream_t sB = nullptr, sM = nullptr;
    static cudaEvent_t evFork, evB, evM;
    if (!sB) {
        cudaStreamCreateWithFlags(&sB, cudaStreamNonBlocking);
        cudaStreamCreateWithFlags(&sM, cudaStreamNonBlocking);
        cudaEventCreateWithFlags(&evFork, cudaEventDisableTiming);
        cudaEventCreateWithFlags(&evB, cudaEventDisableTiming);
        cudaEventCreateWithFlags(&evM, cudaEventDisableTiming);
        cudaFuncSetAttribute(gemm_kernel,
                             cudaFuncAttributeMaxDynamicSharedMemorySize, GEMM_SMEM);
    }

    // fork
    cudaEventRecord(evFork, 0);
    cudaStreamWaitEvent(sB, evFork, 0);
    cudaStreamWaitEvent(sM, evFork, 0);

    // meta branch (side stream)
    meta_kernel<<<1, 256, 0, sM>>>(meta_a, meta_b, fc1w, fc1b, fc2w, fc2b);

    // graph A (legacy stream) + graph B (side stream)
    for (int g = 0; g < 2; g++) {
        const float* x   = g ? x_b : x_a;
        const int*   src = g ? ei_b : ei_a;
        const int*   dst = src + E;
        cudaStream_t st  = g ? sB : (cudaStream_t)0;

        init_kernel<<<nb_nodes, 256, 0, st>>>(N, g);
        count_kernel<<<nb_edges, 256, 0, st>>>(dst, E, g);
        scan_kernel<<<1, 1024, 0, st>>>(N, g);
        fill_kernel<<<nb_edges, 256, 0, st>>>(src, dst, E, g);

        agg_kernel<<<N, F, 0, st>>>(x, g);
        gemm_kernel<<<nb_gemm, 256, GEMM_SMEM, st>>>(gcn1w, gcn1b, N, g);
        agg_kernel<<<N, F, 0, st>>>(nullptr, g);
        gemm_kernel<<<nb_gemm, 256, GEMM_SMEM, st>>>(gcn2w, gcn2b, N, g);
        agg_kernel<<<N, F, 0, st>>>(nullptr, g);
        gemm_kernel<<<nb_gemm, 256, GEMM_SMEM, st>>>(gcn2w, gcn2b, N, g);

        pool_partial_kernel<<<PBLK, F, 0, st>>>(N, g);
    }

    // join
    cudaEventRecord(evB, sB);
    cudaEventRecord(evM, sM);
    cudaStreamWaitEvent(0, evB, 0);
    cudaStreamWaitEvent(0, evM, 0);

    tail_kernel<<<1, 256>>>(fccw, fccb, fcc2w, fcc2b, outw, outb,
                            invN, (float*)d_out);
}

// round 4
// speedup vs baseline: 2.1010x; 1.3271x over previous
#include <cuda_runtime.h>
#include <cuda_bf16.h>
#include <math.h>

// ---------------------------------------------------------------------------
// ProteinInteractionPredictor. GCNConv: Y = relu( Agg(X) @ W + b ).
// Graph A on legacy stream, graph B + meta branch on side streams.
// ---------------------------------------------------------------------------

#define MAXN 50000
#define MAXE 800000
#define F 128
#define PBLK 256
#define SCAN_BLK 1024                 // counts per scan block
#define MAXSB 64                      // max scan blocks (ceil(50000/1024)=49)

__device__ float g_PA[MAXN * F];
__device__ float g_YA[MAXN * F];
__device__ float g_PB[MAXN * F];
__device__ float g_YB[MAXN * F];
__device__ int   g_cntA[MAXN],    g_cntB[MAXN];
__device__ int   g_cursorA[MAXN], g_cursorB[MAXN];
__device__ int   g_offsA[MAXN + 1], g_offsB[MAXN + 1];
__device__ float g_invsA[MAXN],   g_invsB[MAXN];
__device__ int   g_csrA[MAXE],    g_csrB[MAXE];
__device__ int   g_bsum[2][MAXSB];
__device__ int   g_btop[2][MAXSB];
__device__ float g_partial[2 * PBLK * F];
__device__ float g_meta[256];

// ---------------------------------------------------------------------------
// f32x2 helpers
// ---------------------------------------------------------------------------
__device__ __forceinline__ void ffma2(unsigned long long& d,
                                      unsigned long long a, unsigned long long b) {
    asm("fma.rn.f32x2 %0, %1, %2, %0;" : "+l"(d) : "l"(a), "l"(b));
}
__device__ __forceinline__ unsigned long long pack2(float x, float y) {
    unsigned long long r;
    asm("mov.b64 %0, {%1, %2};" : "=l"(r) : "f"(x), "f"(y));
    return r;
}
__device__ __forceinline__ float f2lo(unsigned long long v) {
    return __uint_as_float((unsigned)v);
}
__device__ __forceinline__ float f2hi(unsigned long long v) {
    return __uint_as_float((unsigned)(v >> 32));
}

// ---------------------------------------------------------------------------
// CSR build
// ---------------------------------------------------------------------------
__global__ void init_kernel(int n, int gb) {
    int* cnt = gb ? g_cntB : g_cntA;
    int* cur = gb ? g_cursorB : g_cursorA;
    int i = blockIdx.x * blockDim.x + threadIdx.x;
    if (i < n) { cnt[i] = 0; cur[i] = 0; }
}

__global__ void count_kernel(const int* __restrict__ dst, int e_cnt, int gb) {
    int* cnt = gb ? g_cntB : g_cntA;
    int e = blockIdx.x * blockDim.x + threadIdx.x;
    if (e < e_cnt) atomicAdd(&cnt[dst[e]], 1);
}

// phase 1: per-block sums (256 thr x 4 elems = 1024 counts per block)
__global__ __launch_bounds__(256) void scan_sum_kernel(int n, int gb) {
    const int* cnt = gb ? g_cntB : g_cntA;
    __shared__ int wsum[8];
    int t = threadIdx.x;
    int base = blockIdx.x * SCAN_BLK + t * 4;
    int s = 0;
#pragma unroll
    for (int k = 0; k < 4; k++) {
        int i = base + k;
        if (i < n) s += cnt[i];
    }
    int lane = t & 31, wid = t >> 5;
#pragma unroll
    for (int d = 16; d > 0; d >>= 1) s += __shfl_down_sync(0xffffffffu, s, d);
    if (lane == 0) wsum[wid] = s;
    __syncthreads();
    if (t == 0) {
        int r = 0;
#pragma unroll
        for (int w = 0; w < 8; w++) r += wsum[w];
        g_bsum[gb][blockIdx.x] = r;
    }
}

// phase 2: scan block sums (single block, 64 threads, Hillis-Steele in smem)
__global__ __launch_bounds__(64) void scan_top_kernel(int nb, int gb) {
    __shared__ int sh[64];
    int t = threadIdx.x;
    int v = (t < nb) ? g_bsum[gb][t] : 0;
    sh[t] = v;
    __syncthreads();
#pragma unroll
    for (int d = 1; d < 64; d <<= 1) {
        int u = (t >= d) ? sh[t - d] : 0;
        __syncthreads();
        sh[t] += u;
        __syncthreads();
    }
    if (t < nb) g_btop[gb][t] = sh[t] - v;   // exclusive
}

// phase 3: block-level exclusive scan + writeback of offs / invs
__global__ __launch_bounds__(256) void scan_out_kernel(int n, int gb) {
    const int* cnt  = gb ? g_cntB : g_cntA;
    int*       offs = gb ? g_offsB : g_offsA;
    float*     invs = gb ? g_invsB : g_invsA;
    __shared__ int wsum[8];
    int t = threadIdx.x;
    int lane = t & 31, wid = t >> 5;
    int base = blockIdx.x * SCAN_BLK + t * 4;
    int c[4];
    int s = 0;
#pragma unroll
    for (int k = 0; k < 4; k++) {
        int i = base + k;
        c[k] = (i < n) ? cnt[i] : 0;
        s += c[k];
    }
    // warp inclusive scan of per-thread sums
    int ps = s;
#pragma unroll
    for (int d = 1; d < 32; d <<= 1) {
        int v = __shfl_up_sync(0xffffffffu, ps, d);
        if (lane >= d) ps += v;
    }
    if (lane == 31) wsum[wid] = ps;
    __syncthreads();
    if (t == 0) {
        int r = 0;
#pragma unroll
        for (int w = 0; w < 8; w++) { int v = wsum[w]; wsum[w] = r; r += v; }
    }
    __syncthreads();
    int off = g_btop[gb][blockIdx.x] + wsum[wid] + (ps - s);
#pragma unroll
    for (int k = 0; k < 4; k++) {
        int i = base + k;
        if (i < n) {
            offs[i] = off;
            invs[i] = rsqrtf((float)(c[k] + 1));
            off += c[k];
            if (i == n - 1) offs[n] = off;
        }
    }
}

__global__ void fill_kernel(const int* __restrict__ src, const int* __restrict__ dst,
                            int e_cnt, int gb) {
    int* cur  = gb ? g_cursorB : g_cursorA;
    int* offs = gb ? g_offsB : g_offsA;
    int* csr  = gb ? g_csrB : g_csrA;
    int e = blockIdx.x * blockDim.x + threadIdx.x;
    if (e < e_cnt) {
        int d = dst[e];
        int p = atomicAdd(&cur[d], 1);
        csr[offs[d] + p] = src[e];
    }
}

// ---------------------------------------------------------------------------
// Aggregation: warp per node, lane = float4 column.
// P[i] = inv[i]*( sum_e inv[src]*X[src] + inv[i]*X[i] )
// ---------------------------------------------------------------------------
__global__ __launch_bounds__(256) void agg_kernel(const float* __restrict__ x_ext,
                                                  int n, int gb) {
    const int*   offs = gb ? g_offsB : g_offsA;
    const float* invs = gb ? g_invsB : g_invsA;
    const int*   csr  = gb ? g_csrB : g_csrA;
    const float4* __restrict__ X4 = reinterpret_cast<const float4*>(
        x_ext ? x_ext : (gb ? g_YB : g_YA));
    float4* __restrict__ P4 = reinterpret_cast<float4*>(gb ? g_PB : g_PA);

    int warp = threadIdx.x >> 5;
    int lane = threadIdx.x & 31;
    int i = blockIdx.x * 8 + warp;
    if (i >= n) return;

    int beg = offs[i];
    int end = offs[i + 1];
    float inv_i = invs[i];

    float4 xv = X4[i * 32 + lane];
    float4 acc;
    acc.x = inv_i * xv.x; acc.y = inv_i * xv.y;
    acc.z = inv_i * xv.z; acc.w = inv_i * xv.w;

    for (int base = beg; base < end; base += 32) {
        int cnt = end - base;
        if (cnt > 32) cnt = 32;
        int s = 0; float w = 0.f;
        if (lane < cnt) {
            s = csr[base + lane];
            w = invs[s];
        }
        for (int t = 0; t < cnt; t++) {
            int   ss = __shfl_sync(0xffffffffu, s, t);
            float ww = __shfl_sync(0xffffffffu, w, t);
            float4 v = X4[ss * 32 + lane];
            acc.x += ww * v.x; acc.y += ww * v.y;
            acc.z += ww * v.z; acc.w += ww * v.w;
        }
    }
    float4 o;
    o.x = inv_i * acc.x; o.y = inv_i * acc.y;
    o.z = inv_i * acc.z; o.w = inv_i * acc.w;
    P4[i * 32 + lane] = o;
}

// ---------------------------------------------------------------------------
// GEMM + bias + relu via packed f32x2 FMA. Y = relu(P @ W + b).
// ---------------------------------------------------------------------------
#define GBM 128
#define GBK 32
#define ASTRIDE 130
#define GEMM_SMEM ((F * F + GBK * ASTRIDE) * 4)

__global__ __launch_bounds__(256) void gemm_kernel(const float* __restrict__ W,
                                                   const float* __restrict__ bias,
                                                   int M, int gb) {
    extern __shared__ float sm[];
    float* Ws = sm;
    float* As = sm + F * F;

    const float* __restrict__ A = gb ? g_PB : g_PA;
    float* __restrict__ Y = gb ? g_YB : g_YA;

    int tid = threadIdx.x;
    int tx = tid & 31;
    int ty = tid >> 5;
    int tx4 = tx * 4;
    int ty16 = ty * 16;
    int row0 = blockIdx.x * GBM;

#pragma unroll
    for (int l = 0; l < 16; l++) {
        int idx = tid + l * 256;
        int k = idx >> 5;
        int n4 = (idx & 31) * 4;
        *reinterpret_cast<float4*>(&Ws[k * F + n4]) =
            *reinterpret_cast<const float4*>(W + k * F + n4);
    }

    unsigned long long acc[8][4];
#pragma unroll
    for (int p = 0; p < 8; p++)
#pragma unroll
        for (int j = 0; j < 4; j++) acc[p][j] = 0ULL;

    for (int k0 = 0; k0 < F; k0 += GBK) {
#pragma unroll
        for (int l = 0; l < 4; l++) {
            int idx = tid + l * 256;
            int m = idx >> 3;
            int kc = idx & 7;
            float4 v = make_float4(0.f, 0.f, 0.f, 0.f);
            int gr = row0 + m;
            if (gr < M)
                v = *reinterpret_cast<const float4*>(A + gr * F + k0 + kc * 4);
            As[(kc * 4 + 0) * ASTRIDE + m] = v.x;
            As[(kc * 4 + 1) * ASTRIDE + m] = v.y;
            As[(kc * 4 + 2) * ASTRIDE + m] = v.z;
            As[(kc * 4 + 3) * ASTRIDE + m] = v.w;
        }
        __syncthreads();

#pragma unroll 8
        for (int k = 0; k < GBK; k++) {
            float4 b = *reinterpret_cast<const float4*>(&Ws[(k0 + k) * F + tx4]);
            unsigned long long bx = pack2(b.x, b.x);
            unsigned long long by = pack2(b.y, b.y);
            unsigned long long bz = pack2(b.z, b.z);
            unsigned long long bw = pack2(b.w, b.w);
            const unsigned long long* ar =
                reinterpret_cast<const unsigned long long*>(&As[k * ASTRIDE + ty16]);
#pragma unroll
            for (int p = 0; p < 8; p++) {
                unsigned long long a2 = ar[p];
                ffma2(acc[p][0], a2, bx);
                ffma2(acc[p][1], a2, by);
                ffma2(acc[p][2], a2, bz);
                ffma2(acc[p][3], a2, bw);
            }
        }
        __syncthreads();
    }

    float4 bv = *reinterpret_cast<const float4*>(bias + tx4);
#pragma unroll
    for (int p = 0; p < 8; p++) {
        int gr = row0 + ty16 + 2 * p;
        if (gr < M) {
            float4 o;
            o.x = fmaxf(f2lo(acc[p][0]) + bv.x, 0.f);
            o.y = fmaxf(f2lo(acc[p][1]) + bv.y, 0.f);
            o.z = fmaxf(f2lo(acc[p][2]) + bv.z, 0.f);
            o.w = fmaxf(f2lo(acc[p][3]) + bv.w, 0.f);
            *reinterpret_cast<float4*>(Y + gr * F + tx4) = o;
        }
        if (gr + 1 < M) {
            float4 o;
            o.x = fmaxf(f2hi(acc[p][0]) + bv.x, 0.f);
            o.y = fmaxf(f2hi(acc[p][1]) + bv.y, 0.f);
            o.z = fmaxf(f2hi(acc[p][2]) + bv.z, 0.f);
            o.w = fmaxf(f2hi(acc[p][3]) + bv.w, 0.f);
            *reinterpret_cast<float4*>(Y + (gr + 1) * F + tx4) = o;
        }
    }
}

// ---------------------------------------------------------------------------
// Pooling partials
// ---------------------------------------------------------------------------
__global__ __launch_bounds__(F) void pool_partial_kernel(int n, int gb) {
    const float* Y = gb ? g_YB : g_YA;
    int j = threadIdx.x;
    float acc = 0.f;
    for (int i = blockIdx.x; i < n; i += gridDim.x)
        acc += Y[i * F + j];
    g_partial[(gb * PBLK + blockIdx.x) * F + j] = acc;
}

// ---------------------------------------------------------------------------
// Meta branch
// ---------------------------------------------------------------------------
__global__ __launch_bounds__(256) void meta_kernel(
    const float* __restrict__ ma, const float* __restrict__ mb,
    const float* __restrict__ fc1w, const float* __restrict__ fc1b,
    const float* __restrict__ fc2w, const float* __restrict__ fc2b)
{
    __shared__ float s1a[256], s1b[256];
    int t = threadIdx.x;
    float accA = 0.f, accB = 0.f;
    for (int k = 0; k < 1024; k++) {
        float w = fc1w[k * 256 + t];
        accA += ma[k] * w;
        accB += mb[k] * w;
    }
    s1a[t] = fmaxf(accA + fc1b[t], 0.f);
    s1b[t] = fmaxf(accB + fc1b[t], 0.f);
    __syncthreads();
    if (t < 128) {
        float oA = 0.f, oB = 0.f;
        for (int k = 0; k < 256; k++) {
            float w = fc2w[k * 128 + t];
            oA += s1a[k] * w;
            oB += s1b[k] * w;
        }
        g_meta[t]       = fmaxf(oA + fc2b[t], 0.f);
        g_meta[128 + t] = fmaxf(oB + fc2b[t], 0.f);
    }
}

// ---------------------------------------------------------------------------
// Tail
// ---------------------------------------------------------------------------
__global__ __launch_bounds__(256) void tail_kernel(
    const float* __restrict__ fccw, const float* __restrict__ fccb,
    const float* __restrict__ fcc2w, const float* __restrict__ fcc2b,
    const float* __restrict__ outw, const float* __restrict__ outb,
    float invN, float* __restrict__ out)
{
    __shared__ float c[512], c1[256], c2[128];
    int t = threadIdx.x;

    if (t < 128) {
        float sa = 0.f, sb = 0.f;
        for (int p = 0; p < PBLK; p++) {
            sa += g_partial[p * F + t];
            sb += g_partial[(PBLK + p) * F + t];
        }
        c[256 + t] = sa * invN;
        c[384 + t] = sb * invN;
        c[t]       = g_meta[t];
        c[128 + t] = g_meta[128 + t];
    }
    __syncthreads();
    {
        float acc = 0.f;
        for (int k = 0; k < 512; k++) acc += c[k] * fccw[k * 256 + t];
        c1[t] = fmaxf(acc + fccb[t], 0.f);
    }
    __syncthreads();
    if (t < 128) {
        float acc = 0.f;
        for (int k = 0; k < 256; k++) acc += c1[k] * fcc2w[k * 128 + t];
        c2[t] = fmaxf(acc + fcc2b[t], 0.f);
    }
    __syncthreads();
    if (t == 0) {
        float s = 0.f;
        for (int k = 0; k < 128; k++) s += c2[k] * outw[k];
        s += outb[0];
        out[0] = 1.f / (1.f + expf(-s));
    }
}

// ---------------------------------------------------------------------------
// Launch
// ---------------------------------------------------------------------------
extern "C" void kernel_launch(void* const* d_in, const int* in_sizes, int n_in,
                              void* d_out, int out_size) {
    const float* meta_a = (const float*)d_in[0];
    const float* meta_b = (const float*)d_in[1];
    const float* x_a    = (const float*)d_in[2];
    const int*   ei_a   = (const int*)  d_in[3];
    const float* x_b    = (const float*)d_in[4];
    const int*   ei_b   = (const int*)  d_in[5];
    const float* fc1w   = (const float*)d_in[6];
    const float* fc1b   = (const float*)d_in[7];
    const float* fc2w   = (const float*)d_in[8];
    const float* fc2b   = (const float*)d_in[9];
    const float* gcn1w  = (const float*)d_in[10];
    const float* gcn1b  = (const float*)d_in[11];
    const float* gcn2w  = (const float*)d_in[12];
    const float* gcn2b  = (const float*)d_in[13];
    const float* fccw   = (const float*)d_in[14];
    const float* fccb   = (const float*)d_in[15];
    const float* fcc2w  = (const float*)d_in[16];
    const float* fcc2b  = (const float*)d_in[17];
    const float* outw   = (const float*)d_in[18];
    const float* outb   = (const float*)d_in[19];

    int N = in_sizes[2] / F;
    int E = in_sizes[3] / 2;

    int nb_nodes = (N + 255) / 256;
    int nb_edges = (E + 255) / 256;
    int nb_gemm  = (N + GBM - 1) / GBM;
    int nb_scan  = (N + SCAN_BLK - 1) / SCAN_BLK;
    int nb_agg   = (N + 7) / 8;
    float invN = 1.0f / (float)N;

    static cudaStream_t sB = nullptr, sM = nullptr;
    static cudaEvent_t evFork, evB, evM;
    if (!sB) {
        cudaStreamCreateWithFlags(&sB, cudaStreamNonBlocking);
        cudaStreamCreateWithFlags(&sM, cudaStreamNonBlocking);
        cudaEventCreateWithFlags(&evFork, cudaEventDisableTiming);
        cudaEventCreateWithFlags(&evB, cudaEventDisableTiming);
        cudaEventCreateWithFlags(&evM, cudaEventDisableTiming);
        cudaFuncSetAttribute(gemm_kernel,
                             cudaFuncAttributeMaxDynamicSharedMemorySize, GEMM_SMEM);
    }

    cudaEventRecord(evFork, 0);
    cudaStreamWaitEvent(sB, evFork, 0);
    cudaStreamWaitEvent(sM, evFork, 0);

    meta_kernel<<<1, 256, 0, sM>>>(meta_a, meta_b, fc1w, fc1b, fc2w, fc2b);

    for (int g = 0; g < 2; g++) {
        const float* x   = g ? x_b : x_a;
        const int*   src = g ? ei_b : ei_a;
        const int*   dst = src + E;
        cudaStream_t st  = g ? sB : (cudaStream_t)0;

        init_kernel<<<nb_nodes, 256, 0, st>>>(N, g);
        count_kernel<<<nb_edges, 256, 0, st>>>(dst, E, g);
        scan_sum_kernel<<<nb_scan, 256, 0, st>>>(N, g);
        scan_top_kernel<<<1, 64, 0, st>>>(nb_scan, g);
        scan_out_kernel<<<nb_scan, 256, 0, st>>>(N, g);
        fill_kernel<<<nb_edges, 256, 0, st>>>(src, dst, E, g);

        agg_kernel<<<nb_agg, 256, 0, st>>>(x, N, g);
        gemm_kernel<<<nb_gemm, 256, GEMM_SMEM, st>>>(gcn1w, gcn1b, N, g);
        agg_kernel<<<nb_agg, 256, 0, st>>>(nullptr, N, g);
        gemm_kernel<<<nb_gemm, 256, GEMM_SMEM, st>>>(gcn2w, gcn2b, N, g);
        agg_kernel<<<nb_agg, 256, 0, st>>>(nullptr, N, g);
        gemm_kernel<<<nb_gemm, 256, GEMM_SMEM, st>>>(gcn2w, gcn2b, N, g);

        pool_partial_kernel<<<PBLK, F, 0, st>>>(N, g);
    }

    cudaEventRecord(evB, sB);
    cudaEventRecord(evM, sM);
    cudaStreamWaitEvent(0, evB, 0);
    cudaStreamWaitEvent(0, evM, 0);

    tail_kernel<<<1, 256>>>(fccw, fccb, fcc2w, fcc2b, outw, outb,
                            invN, (float*)d_out);
}

// round 8
// speedup vs baseline: 2.3591x; 1.1229x over previous
#include <cuda_runtime.h>
#include <cuda_bf16.h>
#include <math.h>

// ---------------------------------------------------------------------------
// ProteinInteractionPredictor. GCNConv: Y = relu( Agg(X) @ W + b ).
// bf16 storage for gathered operands (X/Y), fp32 accumulation everywhere.
// RULE: __device__ globals are NEVER referenced from host code -- kernels
// select their banks via integer flags (host-side &g_X is a host shadow
// address; dereferencing it on device triggers HMM page migration = the
// 128MiB "allocation" the harness guard caught in R5/R6).
// ---------------------------------------------------------------------------

#define MAXN 50000
#define MAXE 800000
#define F 128
#define PBLK 256
#define SCAN_BLK 1024
#define MAXSB 64

__device__ __nv_bfloat16 g_XbfA[MAXN * F];
__device__ __nv_bfloat16 g_XbfB[MAXN * F];
__device__ __nv_bfloat16 g_YA[MAXN * F];
__device__ __nv_bfloat16 g_YB[MAXN * F];
__device__ float g_PA[MAXN * F];
__device__ float g_PB[MAXN * F];
__device__ int   g_cntA[MAXN],    g_cntB[MAXN];
__device__ int   g_cursorA[MAXN], g_cursorB[MAXN];
__device__ int   g_offsA[MAXN + 1], g_offsB[MAXN + 1];
__device__ float g_invsA[MAXN],   g_invsB[MAXN];
__device__ int   g_csrA[MAXE],    g_csrB[MAXE];
__device__ int   g_bsum[2][MAXSB];
__device__ int   g_btop[2][MAXSB];
__device__ float g_partial[2 * PBLK * F];
__device__ float g_meta[256];

// ---------------------------------------------------------------------------
// helpers (register-only)
// ---------------------------------------------------------------------------
__device__ __forceinline__ void ffma2(unsigned long long& d,
                                      unsigned long long a, unsigned long long b) {
    asm("fma.rn.f32x2 %0, %1, %2, %0;" : "+l"(d) : "l"(a), "l"(b));
}
__device__ __forceinline__ unsigned long long pack2(float x, float y) {
    unsigned long long r;
    asm("mov.b64 %0, {%1, %2};" : "=l"(r) : "f"(x), "f"(y));
    return r;
}
__device__ __forceinline__ float f2lo(unsigned long long v) {
    return __uint_as_float((unsigned)v);
}
__device__ __forceinline__ float f2hi(unsigned long long v) {
    return __uint_as_float((unsigned)(v >> 32));
}
__device__ __forceinline__ float bflo(unsigned w) { return __uint_as_float(w << 16); }
__device__ __forceinline__ float bfhi(unsigned w) { return __uint_as_float(w & 0xffff0000u); }
__device__ __forceinline__ unsigned bfpack(float lo, float hi) {
    unsigned r;
    asm("cvt.rn.bf16x2.f32 %0, %1, %2;" : "=r"(r) : "f"(hi), "f"(lo));
    return r;
}

// ---------------------------------------------------------------------------
// fp32 -> bf16 conversion of external inputs
// ---------------------------------------------------------------------------
__global__ void cvt_kernel(const float* __restrict__ x, int n_quads, int gb) {
    uint2* dst = reinterpret_cast<uint2*>(gb ? g_XbfB : g_XbfA);
    int i = blockIdx.x * blockDim.x + threadIdx.x;
    if (i < n_quads) {
        float4 v = reinterpret_cast<const float4*>(x)[i];
        uint2 o;
        o.x = bfpack(v.x, v.y);
        o.y = bfpack(v.z, v.w);
        dst[i] = o;
    }
}

// ---------------------------------------------------------------------------
// CSR build (cnt/cursor zeroed in scan_out, restoring invariant per replay)
// ---------------------------------------------------------------------------
__global__ void count_kernel(const int* __restrict__ dst, int e_cnt, int gb) {
    int* cnt = gb ? g_cntB : g_cntA;
    int e = blockIdx.x * blockDim.x + threadIdx.x;
    if (e < e_cnt) atomicAdd(&cnt[dst[e]], 1);
}

__global__ __launch_bounds__(256) void scan_sum_kernel(int n, int gb) {
    const int* cnt = gb ? g_cntB : g_cntA;
    __shared__ int wsum[8];
    int t = threadIdx.x;
    int base = blockIdx.x * SCAN_BLK + t * 4;
    int s = 0;
#pragma unroll
    for (int k = 0; k < 4; k++) {
        int i = base + k;
        if (i < n) s += cnt[i];
    }
    int lane = t & 31, wid = t >> 5;
#pragma unroll
    for (int d = 16; d > 0; d >>= 1) s += __shfl_down_sync(0xffffffffu, s, d);
    if (lane == 0) wsum[wid] = s;
    __syncthreads();
    if (t == 0) {
        int r = 0;
#pragma unroll
        for (int w = 0; w < 8; w++) r += wsum[w];
        g_bsum[gb][blockIdx.x] = r;
    }
}

__global__ __launch_bounds__(64) void scan_top_kernel(int nb, int gb) {
    __shared__ int sh[64];
    int t = threadIdx.x;
    int v = (t < nb) ? g_bsum[gb][t] : 0;
    sh[t] = v;
    __syncthreads();
#pragma unroll
    for (int d = 1; d < 64; d <<= 1) {
        int u = (t >= d) ? sh[t - d] : 0;
        __syncthreads();
        sh[t] += u;
        __syncthreads();
    }
    if (t < nb) g_btop[gb][t] = sh[t] - v;
}

__global__ __launch_bounds__(256) void scan_out_kernel(int n, int gb) {
    int*   cnt  = gb ? g_cntB : g_cntA;
    int*   cur  = gb ? g_cursorB : g_cursorA;
    int*   offs = gb ? g_offsB : g_offsA;
    float* invs = gb ? g_invsB : g_invsA;
    __shared__ int wsum[8];
    int t = threadIdx.x;
    int lane = t & 31, wid = t >> 5;
    int base = blockIdx.x * SCAN_BLK + t * 4;
    int c[4];
    int s = 0;
#pragma unroll
    for (int k = 0; k < 4; k++) {
        int i = base + k;
        c[k] = (i < n) ? cnt[i] : 0;
        s += c[k];
    }
    int ps = s;
#pragma unroll
    for (int d = 1; d < 32; d <<= 1) {
        int v = __shfl_up_sync(0xffffffffu, ps, d);
        if (lane >= d) ps += v;
    }
    if (lane == 31) wsum[wid] = ps;
    __syncthreads();
    if (t == 0) {
        int r = 0;
#pragma unroll
        for (int w = 0; w < 8; w++) { int v = wsum[w]; wsum[w] = r; r += v; }
    }
    __syncthreads();
    int off = g_btop[gb][blockIdx.x] + wsum[wid] + (ps - s);
#pragma unroll
    for (int k = 0; k < 4; k++) {
        int i = base + k;
        if (i < n) {
            offs[i] = off;
            invs[i] = rsqrtf((float)(c[k] + 1));
            off += c[k];
            cnt[i] = 0;
            cur[i] = 0;
            if (i == n - 1) offs[n] = off;
        }
    }
}

__global__ void fill_kernel(const int* __restrict__ src, const int* __restrict__ dst,
                            int e_cnt, int gb) {
    int* cur  = gb ? g_cursorB : g_cursorA;
    int* offs = gb ? g_offsB : g_offsA;
    int* csr  = gb ? g_csrB : g_csrA;
    int e = blockIdx.x * blockDim.x + threadIdx.x;
    if (e < e_cnt) {
        int d = dst[e];
        int p = atomicAdd(&cur[d], 1);
        csr[offs[d] + p] = src[e];
    }
}

// ---------------------------------------------------------------------------
// Aggregation: warp per node, lane = 4 bf16 columns (8B load), fp32 acc.
// use_y=0: X = g_Xbf{A,B} (converted input); use_y=1: X = g_Y{A,B}.
// ---------------------------------------------------------------------------
__global__ __launch_bounds__(256) void agg_kernel(int use_y, int n, int gb) {
    const int*   offs = gb ? g_offsB : g_offsA;
    const float* invs = gb ? g_invsB : g_invsA;
    const int*   csr  = gb ? g_csrB : g_csrA;
    const __nv_bfloat16* Xb =
        use_y ? (gb ? g_YB : g_YA) : (gb ? g_XbfB : g_XbfA);
    const uint2* __restrict__ X2 = reinterpret_cast<const uint2*>(Xb);
    float4* __restrict__ P4 = reinterpret_cast<float4*>(gb ? g_PB : g_PA);

    int warp = threadIdx.x >> 5;
    int lane = threadIdx.x & 31;
    int i = blockIdx.x * 8 + warp;
    if (i >= n) return;

    int beg = offs[i];
    int end = offs[i + 1];
    float inv_i = invs[i];

    uint2 raw = X2[i * 32 + lane];
    float4 acc;
    acc.x = inv_i * bflo(raw.x); acc.y = inv_i * bfhi(raw.x);
    acc.z = inv_i * bflo(raw.y); acc.w = inv_i * bfhi(raw.y);

    for (int base = beg; base < end; base += 32) {
        int cnt = end - base;
        if (cnt > 32) cnt = 32;
        int s = 0; float w = 0.f;
        if (lane < cnt) {
            s = csr[base + lane];
            w = invs[s];
        }
        for (int t = 0; t < cnt; t++) {
            int   ss = __shfl_sync(0xffffffffu, s, t);
            float ww = __shfl_sync(0xffffffffu, w, t);
            uint2 r = X2[ss * 32 + lane];
            acc.x += ww * bflo(r.x); acc.y += ww * bfhi(r.x);
            acc.z += ww * bflo(r.y); acc.w += ww * bfhi(r.y);
        }
    }
    float4 o;
    o.x = inv_i * acc.x; o.y = inv_i * acc.y;
    o.z = inv_i * acc.z; o.w = inv_i * acc.w;
    P4[i * 32 + lane] = o;
}

// ---------------------------------------------------------------------------
// GEMM + bias + relu, f32x2 FMA; writes Y in bf16 (register-only pack).
// ---------------------------------------------------------------------------
#define GBM 128
#define GBK 32
#define ASTRIDE 130
#define GEMM_SMEM ((F * F + GBK * ASTRIDE) * 4)

__global__ __launch_bounds__(256) void gemm_kernel(const float* __restrict__ W,
                                                   const float* __restrict__ bias,
                                                   int M, int gb) {
    extern __shared__ float sm[];
    float* Ws = sm;
    float* As = sm + F * F;

    const float* __restrict__ A = gb ? g_PB : g_PA;
    uint2* __restrict__ Y2 = reinterpret_cast<uint2*>(gb ? g_YB : g_YA);

    int tid = threadIdx.x;
    int tx = tid & 31;
    int ty = tid >> 5;
    int tx4 = tx * 4;
    int ty16 = ty * 16;
    int row0 = blockIdx.x * GBM;

#pragma unroll
    for (int l = 0; l < 16; l++) {
        int idx = tid + l * 256;
        int k = idx >> 5;
        int n4 = (idx & 31) * 4;
        *reinterpret_cast<float4*>(&Ws[k * F + n4]) =
            *reinterpret_cast<const float4*>(W + k * F + n4);
    }

    unsigned long long acc[8][4];
#pragma unroll
    for (int p = 0; p < 8; p++)
#pragma unroll
        for (int j = 0; j < 4; j++) acc[p][j] = 0ULL;

    for (int k0 = 0; k0 < F; k0 += GBK) {
#pragma unroll
        for (int l = 0; l < 4; l++) {
            int idx = tid + l * 256;
            int m = idx >> 3;
            int kc = idx & 7;
            float4 v = make_float4(0.f, 0.f, 0.f, 0.f);
            int gr = row0 + m;
            if (gr < M)
                v = *reinterpret_cast<const float4*>(A + gr * F + k0 + kc * 4);
            As[(kc * 4 + 0) * ASTRIDE + m] = v.x;
            As[(kc * 4 + 1) * ASTRIDE + m] = v.y;
            As[(kc * 4 + 2) * ASTRIDE + m] = v.z;
            As[(kc * 4 + 3) * ASTRIDE + m] = v.w;
        }
        __syncthreads();

#pragma unroll 8
        for (int k = 0; k < GBK; k++) {
            float4 b = *reinterpret_cast<const float4*>(&Ws[(k0 + k) * F + tx4]);
            unsigned long long bx = pack2(b.x, b.x);
            unsigned long long by = pack2(b.y, b.y);
            unsigned long long bz = pack2(b.z, b.z);
            unsigned long long bw = pack2(b.w, b.w);
            const unsigned long long* ar =
                reinterpret_cast<const unsigned long long*>(&As[k * ASTRIDE + ty16]);
#pragma unroll
            for (int p = 0; p < 8; p++) {
                unsigned long long a2 = ar[p];
                ffma2(acc[p][0], a2, bx);
                ffma2(acc[p][1], a2, by);
                ffma2(acc[p][2], a2, bz);
                ffma2(acc[p][3], a2, bw);
            }
        }
        __syncthreads();
    }

    float4 bv = *reinterpret_cast<const float4*>(bias + tx4);
#pragma unroll
    for (int p = 0; p < 8; p++) {
        int gr = row0 + ty16 + 2 * p;
        if (gr < M) {
            uint2 o;
            o.x = bfpack(fmaxf(f2lo(acc[p][0]) + bv.x, 0.f),
                         fmaxf(f2lo(acc[p][1]) + bv.y, 0.f));
            o.y = bfpack(fmaxf(f2lo(acc[p][2]) + bv.z, 0.f),
                         fmaxf(f2lo(acc[p][3]) + bv.w, 0.f));
            Y2[gr * 32 + tx] = o;
        }
        if (gr + 1 < M) {
            uint2 o;
            o.x = bfpack(fmaxf(f2hi(acc[p][0]) + bv.x, 0.f),
                         fmaxf(f2hi(acc[p][1]) + bv.y, 0.f));
            o.y = bfpack(fmaxf(f2hi(acc[p][2]) + bv.z, 0.f),
                         fmaxf(f2hi(acc[p][3]) + bv.w, 0.f));
            Y2[(gr + 1) * 32 + tx] = o;
        }
    }
}

// ---------------------------------------------------------------------------
// Pooling partials over bf16 Y
// ---------------------------------------------------------------------------
__global__ __launch_bounds__(F) void pool_partial_kernel(int n, int gb) {
    const __nv_bfloat16* Y = gb ? g_YB : g_YA;
    int j = threadIdx.x;
    float acc = 0.f;
    for (int i = blockIdx.x; i < n; i += gridDim.x)
        acc += __bfloat162float(Y[i * F + j]);
    g_partial[(gb * PBLK + blockIdx.x) * F + j] = acc;
}

// ---------------------------------------------------------------------------
// Meta branch
// ---------------------------------------------------------------------------
__global__ __launch_bounds__(256) void meta_kernel(
    const float* __restrict__ ma, const float* __restrict__ mb,
    const float* __restrict__ fc1w, const float* __restrict__ fc1b,
    const float* __restrict__ fc2w, const float* __restrict__ fc2b)
{
    __shared__ float s1a[256], s1b[256];
    int t = threadIdx.x;
    float accA = 0.f, accB = 0.f;
    for (int k = 0; k < 1024; k++) {
        float w = fc1w[k * 256 + t];
        accA += ma[k] * w;
        accB += mb[k] * w;
    }
    s1a[t] = fmaxf(accA + fc1b[t], 0.f);
    s1b[t] = fmaxf(accB + fc1b[t], 0.f);
    __syncthreads();
    if (t < 128) {
        float oA = 0.f, oB = 0.f;
        for (int k = 0; k < 256; k++) {
            float w = fc2w[k * 128 + t];
            oA += s1a[k] * w;
            oB += s1b[k] * w;
        }
        g_meta[t]       = fmaxf(oA + fc2b[t], 0.f);
        g_meta[128 + t] = fmaxf(oB + fc2b[t], 0.f);
    }
}

// ---------------------------------------------------------------------------
// Tail
// ---------------------------------------------------------------------------
__global__ __launch_bounds__(256) void tail_kernel(
    const float* __restrict__ fccw, const float* __restrict__ fccb,
    const float* __restrict__ fcc2w, const float* __restrict__ fcc2b,
    const float* __restrict__ outw, const float* __restrict__ outb,
    float invN, float* __restrict__ out)
{
    __shared__ float c[512], c1[256], c2[128];
    int t = threadIdx.x;

    if (t < 128) {
        float sa = 0.f, sb = 0.f;
        for (int p = 0; p < PBLK; p++) {
            sa += g_partial[p * F + t];
            sb += g_partial[(PBLK + p) * F + t];
        }
        c[256 + t] = sa * invN;
        c[384 + t] = sb * invN;
        c[t]       = g_meta[t];
        c[128 + t] = g_meta[128 + t];
    }
    __syncthreads();
    {
        float acc = 0.f;
        for (int k = 0; k < 512; k++) acc += c[k] * fccw[k * 256 + t];
        c1[t] = fmaxf(acc + fccb[t], 0.f);
    }
    __syncthreads();
    if (t < 128) {
        float acc = 0.f;
        for (int k = 0; k < 256; k++) acc += c1[k] * fcc2w[k * 128 + t];
        c2[t] = fmaxf(acc + fcc2b[t], 0.f);
    }
    __syncthreads();
    if (t == 0) {
        float s = 0.f;
        for (int k = 0; k < 128; k++) s += c2[k] * outw[k];
        s += outb[0];
        out[0] = 1.f / (1.f + expf(-s));
    }
}

// ---------------------------------------------------------------------------
// Launch (no __device__ symbol appears anywhere below)
// ---------------------------------------------------------------------------
extern "C" void kernel_launch(void* const* d_in, const int* in_sizes, int n_in,
                              void* d_out, int out_size) {
    const float* meta_a = (const float*)d_in[0];
    const float* meta_b = (const float*)d_in[1];
    const float* x_a    = (const float*)d_in[2];
    const int*   ei_a   = (const int*)  d_in[3];
    const float* x_b    = (const float*)d_in[4];
    const int*   ei_b   = (const int*)  d_in[5];
    const float* fc1w   = (const float*)d_in[6];
    const float* fc1b   = (const float*)d_in[7];
    const float* fc2w   = (const float*)d_in[8];
    const float* fc2b   = (const float*)d_in[9];
    const float* gcn1w  = (const float*)d_in[10];
    const float* gcn1b  = (const float*)d_in[11];
    const float* gcn2w  = (const float*)d_in[12];
    const float* gcn2b  = (const float*)d_in[13];
    const float* fccw   = (const float*)d_in[14];
    const float* fccb   = (const float*)d_in[15];
    const float* fcc2w  = (const float*)d_in[16];
    const float* fcc2b  = (const float*)d_in[17];
    const float* outw   = (const float*)d_in[18];
    const float* outb   = (const float*)d_in[19];

    int N = in_sizes[2] / F;
    int E = in_sizes[3] / 2;

    int nb_edges = (E + 255) / 256;
    int nb_gemm  = (N + GBM - 1) / GBM;
    int nb_scan  = (N + SCAN_BLK - 1) / SCAN_BLK;
    int nb_agg   = (N + 7) / 8;
    int n_quads  = N * F / 4;
    int nb_cvt   = (n_quads + 255) / 256;
    float invN = 1.0f / (float)N;

    static cudaStream_t sB = nullptr, sM = nullptr;
    static cudaEvent_t evFork, evB, evM;
    if (!sB) {
        cudaStreamCreateWithFlags(&sB, cudaStreamNonBlocking);
        cudaStreamCreateWithFlags(&sM, cudaStreamNonBlocking);
        cudaEventCreateWithFlags(&evFork, cudaEventDisableTiming);
        cudaEventCreateWithFlags(&evB, cudaEventDisableTiming);
        cudaEventCreateWithFlags(&evM, cudaEventDisableTiming);
        cudaFuncSetAttribute(gemm_kernel,
                             cudaFuncAttributeMaxDynamicSharedMemorySize, GEMM_SMEM);
    }

    cudaEventRecord(evFork, 0);
    cudaStreamWaitEvent(sB, evFork, 0);
    cudaStreamWaitEvent(sM, evFork, 0);

    meta_kernel<<<1, 256, 0, sM>>>(meta_a, meta_b, fc1w, fc1b, fc2w, fc2b);

    for (int g = 0; g < 2; g++) {
        const float* x   = g ? x_b : x_a;
        const int*   src = g ? ei_b : ei_a;
        const int*   dst = src + E;
        cudaStream_t st  = g ? sB : (cudaStream_t)0;

        cvt_kernel<<<nb_cvt, 256, 0, st>>>(x, n_quads, g);
        count_kernel<<<nb_edges, 256, 0, st>>>(dst, E, g);
        scan_sum_kernel<<<nb_scan, 256, 0, st>>>(N, g);
        scan_top_kernel<<<1, 64, 0, st>>>(nb_scan, g);
        scan_out_kernel<<<nb_scan, 256, 0, st>>>(N, g);
        fill_kernel<<<nb_edges, 256, 0, st>>>(src, dst, E, g);

        agg_kernel<<<nb_agg, 256, 0, st>>>(0, N, g);
        gemm_kernel<<<nb_gemm, 256, GEMM_SMEM, st>>>(gcn1w, gcn1b, N, g);
        agg_kernel<<<nb_agg, 256, 0, st>>>(1, N, g);
        gemm_kernel<<<nb_gemm, 256, GEMM_SMEM, st>>>(gcn2w, gcn2b, N, g);
        agg_kernel<<<nb_agg, 256, 0, st>>>(1, N, g);
        gemm_kernel<<<nb_gemm, 256, GEMM_SMEM, st>>>(gcn2w, gcn2b, N, g);

        pool_partial_kernel<<<PBLK, F, 0, st>>>(N, g);
    }

    cudaEventRecord(evB, sB);
    cudaEventRecord(evM, sM);
    cudaStreamWaitEvent(0, evB, 0);
    cudaStreamWaitEvent(0, evM, 0);

    tail_kernel<<<1, 256>>>(fccw, fccb, fcc2w, fcc2b, outw, outb,
                            invN, (float*)d_out);
}

// round 9
// speedup vs baseline: 3.1257x; 1.3249x over previous
#include <cuda_runtime.h>
#include <cuda_bf16.h>
#include <math.h>

// ---------------------------------------------------------------------------
// ProteinInteractionPredictor. GCNConv: Y = relu( Agg(X) @ W + b ).
// bf16 storage for all gathered/GEMM operands, fp32 accumulation.
// GEMM on tensor cores (mma.sync m16n8k16 bf16).
// RULE: __device__ globals never referenced from host code (bank flags only).
// ---------------------------------------------------------------------------

#define MAXN 50000
#define MAXE 800000
#define F 128
#define PBLK 256
#define SCAN_BLK 1024
#define MAXSB 64

__device__ __nv_bfloat16 g_XbfA[MAXN * F];
__device__ __nv_bfloat16 g_XbfB[MAXN * F];
__device__ __nv_bfloat16 g_YA[MAXN * F];
__device__ __nv_bfloat16 g_YB[MAXN * F];
__device__ __nv_bfloat16 g_PbfA[MAXN * F];   // aggregated features (GEMM A), bf16
__device__ __nv_bfloat16 g_PbfB[MAXN * F];
__device__ __nv_bfloat16 g_Wbf[2][2][F * F]; // [graph][slot] bf16 weights
__device__ int   g_cntA[MAXN],    g_cntB[MAXN];
__device__ int   g_cursorA[MAXN], g_cursorB[MAXN];
__device__ int   g_offsA[MAXN + 1], g_offsB[MAXN + 1];
__device__ float g_invsA[MAXN],   g_invsB[MAXN];
__device__ int   g_csrA[MAXE],    g_csrB[MAXE];
__device__ int   g_bsum[2][MAXSB];
__device__ int   g_btop[2][MAXSB];
__device__ float g_partial[2 * PBLK * F];
__device__ float g_meta[256];

// ---------------------------------------------------------------------------
// helpers (register-only)
// ---------------------------------------------------------------------------
__device__ __forceinline__ float bflo(unsigned w) { return __uint_as_float(w << 16); }
__device__ __forceinline__ float bfhi(unsigned w) { return __uint_as_float(w & 0xffff0000u); }
__device__ __forceinline__ unsigned bfpack(float lo, float hi) {
    unsigned r;
    asm("cvt.rn.bf16x2.f32 %0, %1, %2;" : "=r"(r) : "f"(hi), "f"(lo));
    return r;
}
__device__ __forceinline__ void ldsm4(unsigned& r0, unsigned& r1, unsigned& r2,
                                      unsigned& r3, unsigned addr) {
    asm volatile("ldmatrix.sync.aligned.m8n8.x4.shared.b16 {%0,%1,%2,%3}, [%4];"
                 : "=r"(r0), "=r"(r1), "=r"(r2), "=r"(r3) : "r"(addr));
}
__device__ __forceinline__ void ldsm4t(unsigned& r0, unsigned& r1, unsigned& r2,
                                       unsigned& r3, unsigned addr) {
    asm volatile("ldmatrix.sync.aligned.m8n8.x4.trans.shared.b16 {%0,%1,%2,%3}, [%4];"
                 : "=r"(r0), "=r"(r1), "=r"(r2), "=r"(r3) : "r"(addr));
}
__device__ __forceinline__ void mma16816(float& c0, float& c1, float& c2, float& c3,
                                         unsigned a0, unsigned a1, unsigned a2, unsigned a3,
                                         unsigned b0, unsigned b1) {
    asm volatile("mma.sync.aligned.m16n8k16.row.col.f32.bf16.bf16.f32 "
                 "{%0,%1,%2,%3}, {%4,%5,%6,%7}, {%8,%9}, {%0,%1,%2,%3};"
                 : "+f"(c0), "+f"(c1), "+f"(c2), "+f"(c3)
                 : "r"(a0), "r"(a1), "r"(a2), "r"(a3), "r"(b0), "r"(b1));
}

// ---------------------------------------------------------------------------
// fp32 -> bf16 conversions
// ---------------------------------------------------------------------------
__global__ void cvt_kernel(const float* __restrict__ x, int n_quads, int gb) {
    uint2* dst = reinterpret_cast<uint2*>(gb ? g_XbfB : g_XbfA);
    int i = blockIdx.x * blockDim.x + threadIdx.x;
    if (i < n_quads) {
        float4 v = reinterpret_cast<const float4*>(x)[i];
        uint2 o;
        o.x = bfpack(v.x, v.y);
        o.y = bfpack(v.z, v.w);
        dst[i] = o;
    }
}

__global__ void cvtw_kernel(const float* __restrict__ w, int gb, int slot) {
    uint2* dst = reinterpret_cast<uint2*>(g_Wbf[gb][slot]);
    int i = blockIdx.x * blockDim.x + threadIdx.x;
    if (i < F * F / 4) {
        float4 v = reinterpret_cast<const float4*>(w)[i];
        uint2 o;
        o.x = bfpack(v.x, v.y);
        o.y = bfpack(v.z, v.w);
        dst[i] = o;
    }
}

// ---------------------------------------------------------------------------
// CSR build (cnt/cursor zeroed in scan_out, restoring invariant per replay)
// ---------------------------------------------------------------------------
__global__ void count_kernel(const int* __restrict__ dst, int e_cnt, int gb) {
    int* cnt = gb ? g_cntB : g_cntA;
    int e = blockIdx.x * blockDim.x + threadIdx.x;
    if (e < e_cnt) atomicAdd(&cnt[dst[e]], 1);
}

__global__ __launch_bounds__(256) void scan_sum_kernel(int n, int gb) {
    const int* cnt = gb ? g_cntB : g_cntA;
    __shared__ int wsum[8];
    int t = threadIdx.x;
    int base = blockIdx.x * SCAN_BLK + t * 4;
    int s = 0;
#pragma unroll
    for (int k = 0; k < 4; k++) {
        int i = base + k;
        if (i < n) s += cnt[i];
    }
    int lane = t & 31, wid = t >> 5;
#pragma unroll
    for (int d = 16; d > 0; d >>= 1) s += __shfl_down_sync(0xffffffffu, s, d);
    if (lane == 0) wsum[wid] = s;
    __syncthreads();
    if (t == 0) {
        int r = 0;
#pragma unroll
        for (int w = 0; w < 8; w++) r += wsum[w];
        g_bsum[gb][blockIdx.x] = r;
    }
}

__global__ __launch_bounds__(64) void scan_top_kernel(int nb, int gb) {
    __shared__ int sh[64];
    int t = threadIdx.x;
    int v = (t < nb) ? g_bsum[gb][t] : 0;
    sh[t] = v;
    __syncthreads();
#pragma unroll
    for (int d = 1; d < 64; d <<= 1) {
        int u = (t >= d) ? sh[t - d] : 0;
        __syncthreads();
        sh[t] += u;
        __syncthreads();
    }
    if (t < nb) g_btop[gb][t] = sh[t] - v;
}

__global__ __launch_bounds__(256) void scan_out_kernel(int n, int gb) {
    int*   cnt  = gb ? g_cntB : g_cntA;
    int*   cur  = gb ? g_cursorB : g_cursorA;
    int*   offs = gb ? g_offsB : g_offsA;
    float* invs = gb ? g_invsB : g_invsA;
    __shared__ int wsum[8];
    int t = threadIdx.x;
    int lane = t & 31, wid = t >> 5;
    int base = blockIdx.x * SCAN_BLK + t * 4;
    int c[4];
    int s = 0;
#pragma unroll
    for (int k = 0; k < 4; k++) {
        int i = base + k;
        c[k] = (i < n) ? cnt[i] : 0;
        s += c[k];
    }
    int ps = s;
#pragma unroll
    for (int d = 1; d < 32; d <<= 1) {
        int v = __shfl_up_sync(0xffffffffu, ps, d);
        if (lane >= d) ps += v;
    }
    if (lane == 31) wsum[wid] = ps;
    __syncthreads();
    if (t == 0) {
        int r = 0;
#pragma unroll
        for (int w = 0; w < 8; w++) { int v = wsum[w]; wsum[w] = r; r += v; }
    }
    __syncthreads();
    int off = g_btop[gb][blockIdx.x] + wsum[wid] + (ps - s);
#pragma unroll
    for (int k = 0; k < 4; k++) {
        int i = base + k;
        if (i < n) {
            offs[i] = off;
            invs[i] = rsqrtf((float)(c[k] + 1));
            off += c[k];
            cnt[i] = 0;
            cur[i] = 0;
            if (i == n - 1) offs[n] = off;
        }
    }
}

__global__ void fill_kernel(const int* __restrict__ src, const int* __restrict__ dst,
                            int e_cnt, int gb) {
    int* cur  = gb ? g_cursorB : g_cursorA;
    int* offs = gb ? g_offsB : g_offsA;
    int* csr  = gb ? g_csrB : g_csrA;
    int e = blockIdx.x * blockDim.x + threadIdx.x;
    if (e < e_cnt) {
        int d = dst[e];
        int p = atomicAdd(&cur[d], 1);
        csr[offs[d] + p] = src[e];
    }
}

// ---------------------------------------------------------------------------
// Aggregation: warp per node, lane = 4 bf16 columns (8B load), fp32 acc.
// Writes P in bf16.
// ---------------------------------------------------------------------------
__global__ __launch_bounds__(256) void agg_kernel(int use_y, int n, int gb) {
    const int*   offs = gb ? g_offsB : g_offsA;
    const float* invs = gb ? g_invsB : g_invsA;
    const int*   csr  = gb ? g_csrB : g_csrA;
    const __nv_bfloat16* Xb =
        use_y ? (gb ? g_YB : g_YA) : (gb ? g_XbfB : g_XbfA);
    const uint2* __restrict__ X2 = reinterpret_cast<const uint2*>(Xb);
    uint2* __restrict__ P2 = reinterpret_cast<uint2*>(gb ? g_PbfB : g_PbfA);

    int warp = threadIdx.x >> 5;
    int lane = threadIdx.x & 31;
    int i = blockIdx.x * 8 + warp;
    if (i >= n) return;

    int beg = offs[i];
    int end = offs[i + 1];
    float inv_i = invs[i];

    uint2 raw = X2[i * 32 + lane];
    float4 acc;
    acc.x = inv_i * bflo(raw.x); acc.y = inv_i * bfhi(raw.x);
    acc.z = inv_i * bflo(raw.y); acc.w = inv_i * bfhi(raw.y);

    for (int base = beg; base < end; base += 32) {
        int cnt = end - base;
        if (cnt > 32) cnt = 32;
        int s = 0; float w = 0.f;
        if (lane < cnt) {
            s = csr[base + lane];
            w = invs[s];
        }
        for (int t = 0; t < cnt; t++) {
            int   ss = __shfl_sync(0xffffffffu, s, t);
            float ww = __shfl_sync(0xffffffffu, w, t);
            uint2 r = X2[ss * 32 + lane];
            acc.x += ww * bflo(r.x); acc.y += ww * bfhi(r.x);
            acc.z += ww * bflo(r.y); acc.w += ww * bfhi(r.y);
        }
    }
    uint2 o;
    o.x = bfpack(inv_i * acc.x, inv_i * acc.y);
    o.y = bfpack(inv_i * acc.z, inv_i * acc.w);
    P2[i * 32 + lane] = o;
}

// ---------------------------------------------------------------------------
// Tensor-core GEMM + bias + relu: Y[M,128] = relu(P @ W + b), all bf16 in,
// fp32 accum, bf16 out. Block: 128 rows, 256 threads (8 warps: 4 wm x 2 wn).
// Whole A tile + whole W staged in smem (stride 136 bf16 -> conflict-free
// ldmatrix), single __syncthreads, 8 k-iters of mma.m16n8k16.
// ---------------------------------------------------------------------------
#define TS 136
#define GEMM_SMEM (2 * F * TS * 2)   // A + W in bf16 = 69632 B

__global__ __launch_bounds__(256) void gemm_kernel(const float* __restrict__ bias,
                                                   int M, int gb, int wslot) {
    extern __shared__ char sm[];
    char* sA = sm;
    char* sW = sm + F * TS * 2;

    const uint4* __restrict__ Pg =
        reinterpret_cast<const uint4*>(gb ? g_PbfB : g_PbfA);
    const uint4* __restrict__ Wg = reinterpret_cast<const uint4*>(g_Wbf[gb][wslot]);
    unsigned* __restrict__ Yu = reinterpret_cast<unsigned*>(gb ? g_YB : g_YA);

    int tid = threadIdx.x;
    int lane = tid & 31;
    int wid = tid >> 5;
    int wm = wid >> 1;            // 0..3 -> 32-row band
    int wn = wid & 1;             // 0..1 -> 64-col band
    int blockRow = blockIdx.x * F;

    // stage A (row-guarded) and W; 16B chunks, conflict-free stores
#pragma unroll
    for (int l = 0; l < 8; l++) {
        int idx = tid + l * 256;          // 0..2047
        int r = idx >> 4;                 // 0..127
        int c16 = idx & 15;               // 16B chunk in row
        uint4 v = make_uint4(0u, 0u, 0u, 0u);
        int gr = blockRow + r;
        if (gr < M) v = Pg[gr * 16 + c16];
        *reinterpret_cast<uint4*>(sA + r * (TS * 2) + c16 * 16) = v;
        *reinterpret_cast<uint4*>(sW + r * (TS * 2) + c16 * 16) = Wg[r * 16 + c16];
    }
    __syncthreads();

    unsigned baseA = (unsigned)__cvta_generic_to_shared(sA);
    unsigned baseW = (unsigned)__cvta_generic_to_shared(sW);

    float c[2][8][4];
#pragma unroll
    for (int i = 0; i < 2; i++)
#pragma unroll
        for (int j = 0; j < 8; j++)
#pragma unroll
            for (int q = 0; q < 4; q++) c[i][j][q] = 0.f;

#pragma unroll
    for (int k0 = 0; k0 < F; k0 += 16) {
        unsigned a0[4], a1[4];
        int arow = wm * 32 + (lane & 15);
        int ac   = k0 + ((lane >> 4) << 3);
        ldsm4(a0[0], a0[1], a0[2], a0[3], baseA + (arow * TS + ac) * 2);
        ldsm4(a1[0], a1[1], a1[2], a1[3], baseA + ((arow + 16) * TS + ac) * 2);
#pragma unroll
        for (int jj = 0; jj < 4; jj++) {
            unsigned b0, b1, b2, b3;
            int krow = k0 + (lane & 15);
            int nc   = wn * 64 + jj * 16 + ((lane >> 4) << 3);
            ldsm4t(b0, b1, b2, b3, baseW + (krow * TS + nc) * 2);
            mma16816(c[0][2*jj][0], c[0][2*jj][1], c[0][2*jj][2], c[0][2*jj][3],
                     a0[0], a0[1], a0[2], a0[3], b0, b1);
            mma16816(c[0][2*jj+1][0], c[0][2*jj+1][1], c[0][2*jj+1][2], c[0][2*jj+1][3],
                     a0[0], a0[1], a0[2], a0[3], b2, b3);
            mma16816(c[1][2*jj][0], c[1][2*jj][1], c[1][2*jj][2], c[1][2*jj][3],
                     a1[0], a1[1], a1[2], a1[3], b0, b1);
            mma16816(c[1][2*jj+1][0], c[1][2*jj+1][1], c[1][2*jj+1][2], c[1][2*jj+1][3],
                     a1[0], a1[1], a1[2], a1[3], b2, b3);
        }
    }

    // epilogue: bias + relu + bf16 pack (cols come in adjacent pairs)
#pragma unroll
    for (int i = 0; i < 2; i++) {
#pragma unroll
        for (int j = 0; j < 8; j++) {
            int r   = blockRow + wm * 32 + i * 16 + (lane >> 2);
            int col = wn * 64 + j * 8 + 2 * (lane & 3);
            float2 bv = *reinterpret_cast<const float2*>(bias + col);
            if (r < M)
                Yu[r * 64 + (col >> 1)] =
                    bfpack(fmaxf(c[i][j][0] + bv.x, 0.f),
                           fmaxf(c[i][j][1] + bv.y, 0.f));
            if (r + 8 < M)
                Yu[(r + 8) * 64 + (col >> 1)] =
                    bfpack(fmaxf(c[i][j][2] + bv.x, 0.f),
                           fmaxf(c[i][j][3] + bv.y, 0.f));
        }
    }
}

// ---------------------------------------------------------------------------
// Pooling partials over bf16 Y
// ---------------------------------------------------------------------------
__global__ __launch_bounds__(F) void pool_partial_kernel(int n, int gb) {
    const __nv_bfloat16* Y = gb ? g_YB : g_YA;
    int j = threadIdx.x;
    float acc = 0.f;
    for (int i = blockIdx.x; i < n; i += gridDim.x)
        acc += __bfloat162float(Y[i * F + j]);
    g_partial[(gb * PBLK + blockIdx.x) * F + j] = acc;
}

// ---------------------------------------------------------------------------
// Meta branch
// ---------------------------------------------------------------------------
__global__ __launch_bounds__(256) void meta_kernel(
    const float* __restrict__ ma, const float* __restrict__ mb,
    const float* __restrict__ fc1w, const float* __restrict__ fc1b,
    const float* __restrict__ fc2w, const float* __restrict__ fc2b)
{
    __shared__ float s1a[256], s1b[256];
    int t = threadIdx.x;
    float accA = 0.f, accB = 0.f;
    for (int k = 0; k < 1024; k++) {
        float w = fc1w[k * 256 + t];
        accA += ma[k] * w;
        accB += mb[k] * w;
    }
    s1a[t] = fmaxf(accA + fc1b[t], 0.f);
    s1b[t] = fmaxf(accB + fc1b[t], 0.f);
    __syncthreads();
    if (t < 128) {
        float oA = 0.f, oB = 0.f;
        for (int k = 0; k < 256; k++) {
            float w = fc2w[k * 128 + t];
            oA += s1a[k] * w;
            oB += s1b[k] * w;
        }
        g_meta[t]       = fmaxf(oA + fc2b[t], 0.f);
        g_meta[128 + t] = fmaxf(oB + fc2b[t], 0.f);
    }
}

// ---------------------------------------------------------------------------
// Tail
// ---------------------------------------------------------------------------
__global__ __launch_bounds__(256) void tail_kernel(
    const float* __restrict__ fccw, const float* __restrict__ fccb,
    const float* __restrict__ fcc2w, const float* __restrict__ fcc2b,
    const float* __restrict__ outw, const float* __restrict__ outb,
    float invN, float* __restrict__ out)
{
    __shared__ float c[512], c1[256], c2[128];
    int t = threadIdx.x;

    if (t < 128) {
        float sa = 0.f, sb = 0.f;
        for (int p = 0; p < PBLK; p++) {
            sa += g_partial[p * F + t];
            sb += g_partial[(PBLK + p) * F + t];
        }
        c[256 + t] = sa * invN;
        c[384 + t] = sb * invN;
        c[t]       = g_meta[t];
        c[128 + t] = g_meta[128 + t];
    }
    __syncthreads();
    {
        float acc = 0.f;
        for (int k = 0; k < 512; k++) acc += c[k] * fccw[k * 256 + t];
        c1[t] = fmaxf(acc + fccb[t], 0.f);
    }
    __syncthreads();
    if (t < 128) {
        float acc = 0.f;
        for (int k = 0; k < 256; k++) acc += c1[k] * fcc2w[k * 128 + t];
        c2[t] = fmaxf(acc + fcc2b[t], 0.f);
    }
    __syncthreads();
    if (t == 0) {
        float s = 0.f;
        for (int k = 0; k < 128; k++) s += c2[k] * outw[k];
        s += outb[0];
        out[0] = 1.f / (1.f + expf(-s));
    }
}

// ---------------------------------------------------------------------------
// Launch (no __device__ symbol appears anywhere below)
// ---------------------------------------------------------------------------
extern "C" void kernel_launch(void* const* d_in, const int* in_sizes, int n_in,
                              void* d_out, int out_size) {
    const float* meta_a = (const float*)d_in[0];
    const float* meta_b = (const float*)d_in[1];
    const float* x_a    = (const float*)d_in[2];
    const int*   ei_a   = (const int*)  d_in[3];
    const float* x_b    = (const float*)d_in[4];
    const int*   ei_b   = (const int*)  d_in[5];
    const float* fc1w   = (const float*)d_in[6];
    const float* fc1b   = (const float*)d_in[7];
    const float* fc2w   = (const float*)d_in[8];
    const float* fc2b   = (const float*)d_in[9];
    const float* gcn1w  = (const float*)d_in[10];
    const float* gcn1b  = (const float*)d_in[11];
    const float* gcn2w  = (const float*)d_in[12];
    const float* gcn2b  = (const float*)d_in[13];
    const float* fccw   = (const float*)d_in[14];
    const float* fccb   = (const float*)d_in[15];
    const float* fcc2w  = (const float*)d_in[16];
    const float* fcc2b  = (const float*)d_in[17];
    const float* outw   = (const float*)d_in[18];
    const float* outb   = (const float*)d_in[19];

    int N = in_sizes[2] / F;
    int E = in_sizes[3] / 2;

    int nb_edges = (E + 255) / 256;
    int nb_gemm  = (N + F - 1) / F;
    int nb_scan  = (N + SCAN_BLK - 1) / SCAN_BLK;
    int nb_agg   = (N + 7) / 8;
    int n_quads  = N * F / 4;
    int nb_cvt   = (n_quads + 255) / 256;
    int nb_cvtw  = (F * F / 4 + 255) / 256;
    float invN = 1.0f / (float)N;

    static cudaStream_t sB = nullptr, sM = nullptr;
    static cudaEvent_t evFork, evB, evM;
    if (!sB) {
        cudaStreamCreateWithFlags(&sB, cudaStreamNonBlocking);
        cudaStreamCreateWithFlags(&sM, cudaStreamNonBlocking);
        cudaEventCreateWithFlags(&evFork, cudaEventDisableTiming);
        cudaEventCreateWithFlags(&evB, cudaEventDisableTiming);
        cudaEventCreateWithFlags(&evM, cudaEventDisableTiming);
        cudaFuncSetAttribute(gemm_kernel,
                             cudaFuncAttributeMaxDynamicSharedMemorySize, GEMM_SMEM);
    }

    cudaEventRecord(evFork, 0);
    cudaStreamWaitEvent(sB, evFork, 0);
    cudaStreamWaitEvent(sM, evFork, 0);

    meta_kernel<<<1, 256, 0, sM>>>(meta_a, meta_b, fc1w, fc1b, fc2w, fc2b);

    for (int g = 0; g < 2; g++) {
        const float* x   = g ? x_b : x_a;
        const int*   src = g ? ei_b : ei_a;
        const int*   dst = src + E;
        cudaStream_t st  = g ? sB : (cudaStream_t)0;

        cvt_kernel<<<nb_cvt, 256, 0, st>>>(x, n_quads, g);
        cvtw_kernel<<<nb_cvtw, 256, 0, st>>>(gcn1w, g, 0);
        cvtw_kernel<<<nb_cvtw, 256, 0, st>>>(gcn2w, g, 1);
        count_kernel<<<nb_edges, 256, 0, st>>>(dst, E, g);
        scan_sum_kernel<<<nb_scan, 256, 0, st>>>(N, g);
        scan_top_kernel<<<1, 64, 0, st>>>(nb_scan, g);
        scan_out_kernel<<<nb_scan, 256, 0, st>>>(N, g);
        fill_kernel<<<nb_edges, 256, 0, st>>>(src, dst, E, g);

        agg_kernel<<<nb_agg, 256, 0, st>>>(0, N, g);
        gemm_kernel<<<nb_gemm, 256, GEMM_SMEM, st>>>(gcn1b, N, g, 0);
        agg_kernel<<<nb_agg, 256, 0, st>>>(1, N, g);
        gemm_kernel<<<nb_gemm, 256, GEMM_SMEM, st>>>(gcn2b, N, g, 1);
        agg_kernel<<<nb_agg, 256, 0, st>>>(1, N, g);
        gemm_kernel<<<nb_gemm, 256, GEMM_SMEM, st>>>(gcn2b, N, g, 1);

        pool_partial_kernel<<<PBLK, F, 0, st>>>(N, g);
    }

    cudaEventRecord(evB, sB);
    cudaEventRecord(evM, sM);
    cudaStreamWaitEvent(0, evB, 0);
    cudaStreamWaitEvent(0, evM, 0);

    tail_kernel<<<1, 256>>>(fccw, fccb, fcc2w, fcc2b, outw, outb,
                            invN, (float*)d_out);
}

// round 11
// speedup vs baseline: 3.2598x; 1.0429x over previous
#include <cuda_runtime.h>
#include <cuda_bf16.h>
#include <math.h>

// ---------------------------------------------------------------------------
// ProteinInteractionPredictor. GCNConv: Y = relu( Agg(X) @ W + b ).
// bf16 storage, fp32 accumulation, tensor-core GEMM (mma m16n8k16 bf16).
// 3 streams total (legacy=graphA, sB=graphB, sM=conversions+meta) -- the
// 5-stream variant left 2MiB of graph-exec upload pool live after teardown.
// RULE: __device__ globals never referenced from host code (bank flags only).
// ---------------------------------------------------------------------------

#define MAXN 50000
#define MAXE 800000
#define F 128
#define PBLK 256
#define SCAN_BLK 1024
#define MAXSB 64

__device__ __nv_bfloat16 g_XbfA[MAXN * F];
__device__ __nv_bfloat16 g_XbfB[MAXN * F];
__device__ __nv_bfloat16 g_YA[MAXN * F];
__device__ __nv_bfloat16 g_YB[MAXN * F];
__device__ __nv_bfloat16 g_PbfA[MAXN * F];
__device__ __nv_bfloat16 g_PbfB[MAXN * F];
__device__ __nv_bfloat16 g_Wbf[2][2][F * F];
__device__ int   g_cntA[MAXN],    g_cntB[MAXN];
__device__ int   g_cursorA[MAXN], g_cursorB[MAXN];
__device__ int   g_offsA[MAXN + 1], g_offsB[MAXN + 1];
__device__ float g_invsA[MAXN],   g_invsB[MAXN];
__device__ int   g_csrA[MAXE],    g_csrB[MAXE];
__device__ int   g_bsum[2][MAXSB];
__device__ int   g_btop[2][MAXSB];
__device__ float g_partial[2 * PBLK * F];
__device__ float g_meta[256];

// ---------------------------------------------------------------------------
// helpers (register-only)
// ---------------------------------------------------------------------------
__device__ __forceinline__ float bflo(unsigned w) { return __uint_as_float(w << 16); }
__device__ __forceinline__ float bfhi(unsigned w) { return __uint_as_float(w & 0xffff0000u); }
__device__ __forceinline__ unsigned bfpack(float lo, float hi) {
    unsigned r;
    asm("cvt.rn.bf16x2.f32 %0, %1, %2;" : "=r"(r) : "f"(hi), "f"(lo));
    return r;
}
__device__ __forceinline__ void ldsm4(unsigned& r0, unsigned& r1, unsigned& r2,
                                      unsigned& r3, unsigned addr) {
    asm volatile("ldmatrix.sync.aligned.m8n8.x4.shared.b16 {%0,%1,%2,%3}, [%4];"
                 : "=r"(r0), "=r"(r1), "=r"(r2), "=r"(r3) : "r"(addr));
}
__device__ __forceinline__ void ldsm4t(unsigned& r0, unsigned& r1, unsigned& r2,
                                       unsigned& r3, unsigned addr) {
    asm volatile("ldmatrix.sync.aligned.m8n8.x4.trans.shared.b16 {%0,%1,%2,%3}, [%4];"
                 : "=r"(r0), "=r"(r1), "=r"(r2), "=r"(r3) : "r"(addr));
}
__device__ __forceinline__ void mma16816(float& c0, float& c1, float& c2, float& c3,
                                         unsigned a0, unsigned a1, unsigned a2, unsigned a3,
                                         unsigned b0, unsigned b1) {
    asm volatile("mma.sync.aligned.m16n8k16.row.col.f32.bf16.bf16.f32 "
                 "{%0,%1,%2,%3}, {%4,%5,%6,%7}, {%8,%9}, {%0,%1,%2,%3};"
                 : "+f"(c0), "+f"(c1), "+f"(c2), "+f"(c3)
                 : "r"(a0), "r"(a1), "r"(a2), "r"(a3), "r"(b0), "r"(b1));
}

// ---------------------------------------------------------------------------
// fp32 -> bf16 conversions
// ---------------------------------------------------------------------------
__global__ void cvt_kernel(const float* __restrict__ x, int n_quads, int gb) {
    uint2* dst = reinterpret_cast<uint2*>(gb ? g_XbfB : g_XbfA);
    int i = blockIdx.x * blockDim.x + threadIdx.x;
    if (i < n_quads) {
        float4 v = reinterpret_cast<const float4*>(x)[i];
        uint2 o;
        o.x = bfpack(v.x, v.y);
        o.y = bfpack(v.z, v.w);
        dst[i] = o;
    }
}

__global__ void cvtw_kernel(const float* __restrict__ w1,
                            const float* __restrict__ w2, int gb) {
    int i = blockIdx.x * blockDim.x + threadIdx.x;
    int slot = i >= (F * F / 4);
    int j = i - slot * (F * F / 4);
    const float* w = slot ? w2 : w1;
    uint2* dst = reinterpret_cast<uint2*>(g_Wbf[gb][slot]);
    float4 v = reinterpret_cast<const float4*>(w)[j];
    uint2 o;
    o.x = bfpack(v.x, v.y);
    o.y = bfpack(v.z, v.w);
    dst[j] = o;
}

// ---------------------------------------------------------------------------
// CSR build (cnt/cursor zeroed in scan_out, restoring invariant per replay)
// ---------------------------------------------------------------------------
__global__ void count_kernel(const int* __restrict__ dst, int e_cnt, int gb) {
    int* cnt = gb ? g_cntB : g_cntA;
    int e = blockIdx.x * blockDim.x + threadIdx.x;
    if (e < e_cnt) atomicAdd(&cnt[dst[e]], 1);
}

__global__ __launch_bounds__(256) void scan_sum_kernel(int n, int gb) {
    const int* cnt = gb ? g_cntB : g_cntA;
    __shared__ int wsum[8];
    int t = threadIdx.x;
    int base = blockIdx.x * SCAN_BLK + t * 4;
    int s = 0;
#pragma unroll
    for (int k = 0; k < 4; k++) {
        int i = base + k;
        if (i < n) s += cnt[i];
    }
    int lane = t & 31, wid = t >> 5;
#pragma unroll
    for (int d = 16; d > 0; d >>= 1) s += __shfl_down_sync(0xffffffffu, s, d);
    if (lane == 0) wsum[wid] = s;
    __syncthreads();
    if (t == 0) {
        int r = 0;
#pragma unroll
        for (int w = 0; w < 8; w++) r += wsum[w];
        g_bsum[gb][blockIdx.x] = r;
    }
}

__global__ __launch_bounds__(64) void scan_top_kernel(int nb, int gb) {
    __shared__ int sh[64];
    int t = threadIdx.x;
    int v = (t < nb) ? g_bsum[gb][t] : 0;
    sh[t] = v;
    __syncthreads();
#pragma unroll
    for (int d = 1; d < 64; d <<= 1) {
        int u = (t >= d) ? sh[t - d] : 0;
        __syncthreads();
        sh[t] += u;
        __syncthreads();
    }
    if (t < nb) g_btop[gb][t] = sh[t] - v;
}

__global__ __launch_bounds__(256) void scan_out_kernel(int n, int gb) {
    int*   cnt  = gb ? g_cntB : g_cntA;
    int*   cur  = gb ? g_cursorB : g_cursorA;
    int*   offs = gb ? g_offsB : g_offsA;
    float* invs = gb ? g_invsB : g_invsA;
    __shared__ int wsum[8];
    int t = threadIdx.x;
    int lane = t & 31, wid = t >> 5;
    int base = blockIdx.x * SCAN_BLK + t * 4;
    int c[4];
    int s = 0;
#pragma unroll
    for (int k = 0; k < 4; k++) {
        int i = base + k;
        c[k] = (i < n) ? cnt[i] : 0;
        s += c[k];
    }
    int ps = s;
#pragma unroll
    for (int d = 1; d < 32; d <<= 1) {
        int v = __shfl_up_sync(0xffffffffu, ps, d);
        if (lane >= d) ps += v;
    }
    if (lane == 31) wsum[wid] = ps;
    __syncthreads();
    if (t == 0) {
        int r = 0;
#pragma unroll
        for (int w = 0; w < 8; w++) { int v = wsum[w]; wsum[w] = r; r += v; }
    }
    __syncthreads();
    int off = g_btop[gb][blockIdx.x] + wsum[wid] + (ps - s);
#pragma unroll
    for (int k = 0; k < 4; k++) {
        int i = base + k;
        if (i < n) {
            offs[i] = off;
            invs[i] = rsqrtf((float)(c[k] + 1));
            off += c[k];
            cnt[i] = 0;
            cur[i] = 0;
            if (i == n - 1) offs[n] = off;
        }
    }
}

__global__ void fill_kernel(const int* __restrict__ src, const int* __restrict__ dst,
                            int e_cnt, int gb) {
    int* cur  = gb ? g_cursorB : g_cursorA;
    int* offs = gb ? g_offsB : g_offsA;
    int* csr  = gb ? g_csrB : g_csrA;
    int e = blockIdx.x * blockDim.x + threadIdx.x;
    if (e < e_cnt) {
        int d = dst[e];
        int p = atomicAdd(&cur[d], 1);
        csr[offs[d] + p] = src[e];
    }
}

// ---------------------------------------------------------------------------
// Aggregation: warp per node, lane = 4 bf16 columns, fp32 acc, 4-edge unroll.
// ---------------------------------------------------------------------------
__global__ __launch_bounds__(256) void agg_kernel(int use_y, int n, int gb) {
    const int*   offs = gb ? g_offsB : g_offsA;
    const float* invs = gb ? g_invsB : g_invsA;
    const int*   csr  = gb ? g_csrB : g_csrA;
    const __nv_bfloat16* Xb =
        use_y ? (gb ? g_YB : g_YA) : (gb ? g_XbfB : g_XbfA);
    const uint2* __restrict__ X2 = reinterpret_cast<const uint2*>(Xb);
    uint2* __restrict__ P2 = reinterpret_cast<uint2*>(gb ? g_PbfB : g_PbfA);

    int warp = threadIdx.x >> 5;
    int lane = threadIdx.x & 31;
    int i = blockIdx.x * 8 + warp;
    if (i >= n) return;

    int beg = offs[i];
    int end = offs[i + 1];
    float inv_i = invs[i];

    uint2 raw = X2[i * 32 + lane];
    float4 acc;
    acc.x = inv_i * bflo(raw.x); acc.y = inv_i * bfhi(raw.x);
    acc.z = inv_i * bflo(raw.y); acc.w = inv_i * bfhi(raw.y);

    for (int base = beg; base < end; base += 32) {
        int cnt = end - base;
        if (cnt > 32) cnt = 32;
        int s = 0; float w = 0.f;
        if (lane < cnt) {
            s = csr[base + lane];
            w = invs[s];
        }
        int t = 0;
        for (; t + 4 <= cnt; t += 4) {
            int   s0 = __shfl_sync(0xffffffffu, s, t);
            int   s1 = __shfl_sync(0xffffffffu, s, t + 1);
            int   s2 = __shfl_sync(0xffffffffu, s, t + 2);
            int   s3 = __shfl_sync(0xffffffffu, s, t + 3);
            float w0 = __shfl_sync(0xffffffffu, w, t);
            float w1 = __shfl_sync(0xffffffffu, w, t + 1);
            float w2 = __shfl_sync(0xffffffffu, w, t + 2);
            float w3 = __shfl_sync(0xffffffffu, w, t + 3);
            uint2 r0 = X2[s0 * 32 + lane];
            uint2 r1 = X2[s1 * 32 + lane];
            uint2 r2 = X2[s2 * 32 + lane];
            uint2 r3 = X2[s3 * 32 + lane];
            acc.x += w0 * bflo(r0.x); acc.y += w0 * bfhi(r0.x);
            acc.z += w0 * bflo(r0.y); acc.w += w0 * bfhi(r0.y);
            acc.x += w1 * bflo(r1.x); acc.y += w1 * bfhi(r1.x);
            acc.z += w1 * bflo(r1.y); acc.w += w1 * bfhi(r1.y);
            acc.x += w2 * bflo(r2.x); acc.y += w2 * bfhi(r2.x);
            acc.z += w2 * bflo(r2.y); acc.w += w2 * bfhi(r2.y);
            acc.x += w3 * bflo(r3.x); acc.y += w3 * bfhi(r3.x);
            acc.z += w3 * bflo(r3.y); acc.w += w3 * bfhi(r3.y);
        }
        for (; t < cnt; t++) {
            int   ss = __shfl_sync(0xffffffffu, s, t);
            float ww = __shfl_sync(0xffffffffu, w, t);
            uint2 r = X2[ss * 32 + lane];
            acc.x += ww * bflo(r.x); acc.y += ww * bfhi(r.x);
            acc.z += ww * bflo(r.y); acc.w += ww * bfhi(r.y);
        }
    }
    uint2 o;
    o.x = bfpack(inv_i * acc.x, inv_i * acc.y);
    o.y = bfpack(inv_i * acc.z, inv_i * acc.w);
    P2[i * 32 + lane] = o;
}

// ---------------------------------------------------------------------------
// Tensor-core GEMM + bias + relu
// ---------------------------------------------------------------------------
#define TS 136
#define GEMM_SMEM (2 * F * TS * 2)

__global__ __launch_bounds__(256) void gemm_kernel(const float* __restrict__ bias,
                                                   int M, int gb, int wslot) {
    extern __shared__ char sm[];
    char* sA = sm;
    char* sW = sm + F * TS * 2;

    const uint4* __restrict__ Pg =
        reinterpret_cast<const uint4*>(gb ? g_PbfB : g_PbfA);
    const uint4* __restrict__ Wg = reinterpret_cast<const uint4*>(g_Wbf[gb][wslot]);
    unsigned* __restrict__ Yu = reinterpret_cast<unsigned*>(gb ? g_YB : g_YA);

    int tid = threadIdx.x;
    int lane = tid & 31;
    int wid = tid >> 5;
    int wm = wid >> 1;
    int wn = wid & 1;
    int blockRow = blockIdx.x * F;

#pragma unroll
    for (int l = 0; l < 8; l++) {
        int idx = tid + l * 256;
        int r = idx >> 4;
        int c16 = idx & 15;
        uint4 v = make_uint4(0u, 0u, 0u, 0u);
        int gr = blockRow + r;
        if (gr < M) v = Pg[gr * 16 + c16];
        *reinterpret_cast<uint4*>(sA + r * (TS * 2) + c16 * 16) = v;
        *reinterpret_cast<uint4*>(sW + r * (TS * 2) + c16 * 16) = Wg[r * 16 + c16];
    }
    __syncthreads();

    unsigned baseA = (unsigned)__cvta_generic_to_shared(sA);
    unsigned baseW = (unsigned)__cvta_generic_to_shared(sW);

    float c[2][8][4];
#pragma unroll
    for (int i = 0; i < 2; i++)
#pragma unroll
        for (int j = 0; j < 8; j++)
#pragma unroll
            for (int q = 0; q < 4; q++) c[i][j][q] = 0.f;

#pragma unroll
    for (int k0 = 0; k0 < F; k0 += 16) {
        unsigned a0[4], a1[4];
        int arow = wm * 32 + (lane & 15);
        int ac   = k0 + ((lane >> 4) << 3);
        ldsm4(a0[0], a0[1], a0[2], a0[3], baseA + (arow * TS + ac) * 2);
        ldsm4(a1[0], a1[1], a1[2], a1[3], baseA + ((arow + 16) * TS + ac) * 2);
#pragma unroll
        for (int jj = 0; jj < 4; jj++) {
            unsigned b0, b1, b2, b3;
            int krow = k0 + (lane & 15);
            int nc   = wn * 64 + jj * 16 + ((lane >> 4) << 3);
            ldsm4t(b0, b1, b2, b3, baseW + (krow * TS + nc) * 2);
            mma16816(c[0][2*jj][0], c[0][2*jj][1], c[0][2*jj][2], c[0][2*jj][3],
                     a0[0], a0[1], a0[2], a0[3], b0, b1);
            mma16816(c[0][2*jj+1][0], c[0][2*jj+1][1], c[0][2*jj+1][2], c[0][2*jj+1][3],
                     a0[0], a0[1], a0[2], a0[3], b2, b3);
            mma16816(c[1][2*jj][0], c[1][2*jj][1], c[1][2*jj][2], c[1][2*jj][3],
                     a1[0], a1[1], a1[2], a1[3], b0, b1);
            mma16816(c[1][2*jj+1][0], c[1][2*jj+1][1], c[1][2*jj+1][2], c[1][2*jj+1][3],
                     a1[0], a1[1], a1[2], a1[3], b2, b3);
        }
    }

#pragma unroll
    for (int i = 0; i < 2; i++) {
#pragma unroll
        for (int j = 0; j < 8; j++) {
            int r   = blockRow + wm * 32 + i * 16 + (lane >> 2);
            int col = wn * 64 + j * 8 + 2 * (lane & 3);
            float2 bv = *reinterpret_cast<const float2*>(bias + col);
            if (r < M)
                Yu[r * 64 + (col >> 1)] =
                    bfpack(fmaxf(c[i][j][0] + bv.x, 0.f),
                           fmaxf(c[i][j][1] + bv.y, 0.f));
            if (r + 8 < M)
                Yu[(r + 8) * 64 + (col >> 1)] =
                    bfpack(fmaxf(c[i][j][2] + bv.x, 0.f),
                           fmaxf(c[i][j][3] + bv.y, 0.f));
        }
    }
}

// ---------------------------------------------------------------------------
// Pooling partials over bf16 Y
// ---------------------------------------------------------------------------
__global__ __launch_bounds__(F) void pool_partial_kernel(int n, int gb) {
    const __nv_bfloat16* Y = gb ? g_YB : g_YA;
    int j = threadIdx.x;
    float acc = 0.f;
    for (int i = blockIdx.x; i < n; i += gridDim.x)
        acc += __bfloat162float(Y[i * F + j]);
    g_partial[(gb * PBLK + blockIdx.x) * F + j] = acc;
}

// ---------------------------------------------------------------------------
// Meta branch
// ---------------------------------------------------------------------------
__global__ __launch_bounds__(256) void meta_kernel(
    const float* __restrict__ ma, const float* __restrict__ mb,
    const float* __restrict__ fc1w, const float* __restrict__ fc1b,
    const float* __restrict__ fc2w, const float* __restrict__ fc2b)
{
    __shared__ float s1a[256], s1b[256];
    int t = threadIdx.x;
    float accA = 0.f, accB = 0.f;
    for (int k = 0; k < 1024; k++) {
        float w = fc1w[k * 256 + t];
        accA += ma[k] * w;
        accB += mb[k] * w;
    }
    s1a[t] = fmaxf(accA + fc1b[t], 0.f);
    s1b[t] = fmaxf(accB + fc1b[t], 0.f);
    __syncthreads();
    if (t < 128) {
        float oA = 0.f, oB = 0.f;
        for (int k = 0; k < 256; k++) {
            float w = fc2w[k * 128 + t];
            oA += s1a[k] * w;
            oB += s1b[k] * w;
        }
        g_meta[t]       = fmaxf(oA + fc2b[t], 0.f);
        g_meta[128 + t] = fmaxf(oB + fc2b[t], 0.f);
    }
}

// ---------------------------------------------------------------------------
// Tail
// ---------------------------------------------------------------------------
__global__ __launch_bounds__(256) void tail_kernel(
    const float* __restrict__ fccw, const float* __restrict__ fccb,
    const float* __restrict__ fcc2w, const float* __restrict__ fcc2b,
    const float* __restrict__ outw, const float* __restrict__ outb,
    float invN, float* __restrict__ out)
{
    __shared__ float c[512], c1[256], c2[128];
    int t = threadIdx.x;

    if (t < 128) {
        float sa = 0.f, sb = 0.f;
        for (int p = 0; p < PBLK; p++) {
            sa += g_partial[p * F + t];
            sb += g_partial[(PBLK + p) * F + t];
        }
        c[256 + t] = sa * invN;
        c[384 + t] = sb * invN;
        c[t]       = g_meta[t];
        c[128 + t] = g_meta[128 + t];
    }
    __syncthreads();
    {
        float acc = 0.f;
        for (int k = 0; k < 512; k++) acc += c[k] * fccw[k * 256 + t];
        c1[t] = fmaxf(acc + fccb[t], 0.f);
    }
    __syncthreads();
    if (t < 128) {
        float acc = 0.f;
        for (int k = 0; k < 256; k++) acc += c1[k] * fcc2w[k * 128 + t];
        c2[t] = fmaxf(acc + fcc2b[t], 0.f);
    }
    __syncthreads();
    if (t == 0) {
        float s = 0.f;
        for (int k = 0; k < 128; k++) s += c2[k] * outw[k];
        s += outb[0];
        out[0] = 1.f / (1.f + expf(-s));
    }
}

// ---------------------------------------------------------------------------
// Launch (no __device__ symbol appears anywhere below; 3 streams total)
// ---------------------------------------------------------------------------
extern "C" void kernel_launch(void* const* d_in, const int* in_sizes, int n_in,
                              void* d_out, int out_size) {
    const float* meta_a = (const float*)d_in[0];
    const float* meta_b = (const float*)d_in[1];
    const float* x_a    = (const float*)d_in[2];
    const int*   ei_a   = (const int*)  d_in[3];
    const float* x_b    = (const float*)d_in[4];
    const int*   ei_b   = (const int*)  d_in[5];
    const float* fc1w   = (const float*)d_in[6];
    const float* fc1b   = (const float*)d_in[7];
    const float* fc2w   = (const float*)d_in[8];
    const float* fc2b   = (const float*)d_in[9];
    const float* gcn1w  = (const float*)d_in[10];
    const float* gcn1b  = (const float*)d_in[11];
    const float* gcn2w  = (const float*)d_in[12];
    const float* gcn2b  = (const float*)d_in[13];
    const float* fccw   = (const float*)d_in[14];
    const float* fccb   = (const float*)d_in[15];
    const float* fcc2w  = (const float*)d_in[16];
    const float* fcc2b  = (const float*)d_in[17];
    const float* outw   = (const float*)d_in[18];
    const float* outb   = (const float*)d_in[19];

    int N = in_sizes[2] / F;
    int E = in_sizes[3] / 2;

    int nb_edges = (E + 255) / 256;
    int nb_gemm  = (N + F - 1) / F;
    int nb_scan  = (N + SCAN_BLK - 1) / SCAN_BLK;
    int nb_agg   = (N + 7) / 8;
    int n_quads  = N * F / 4;
    int nb_cvt   = (n_quads + 255) / 256;
    int nb_cvtw  = (2 * F * F / 4 + 255) / 256;
    float invN = 1.0f / (float)N;

    static cudaStream_t sB = nullptr, sM = nullptr;
    static cudaEvent_t evFork, evB, evM, evCvt[2];
    if (!sB) {
        cudaStreamCreateWithFlags(&sB, cudaStreamNonBlocking);
        cudaStreamCreateWithFlags(&sM, cudaStreamNonBlocking);
        cudaEventCreateWithFlags(&evFork, cudaEventDisableTiming);
        cudaEventCreateWithFlags(&evB, cudaEventDisableTiming);
        cudaEventCreateWithFlags(&evM, cudaEventDisableTiming);
        cudaEventCreateWithFlags(&evCvt[0], cudaEventDisableTiming);
        cudaEventCreateWithFlags(&evCvt[1], cudaEventDisableTiming);
        cudaFuncSetAttribute(gemm_kernel,
                             cudaFuncAttributeMaxDynamicSharedMemorySize, GEMM_SMEM);
    }

    cudaEventRecord(evFork, 0);
    cudaStreamWaitEvent(sB, evFork, 0);
    cudaStreamWaitEvent(sM, evFork, 0);

    // sM: conversions for both graphs (overlapping the CSR builds), then meta
    cvt_kernel<<<nb_cvt, 256, 0, sM>>>(x_a, n_quads, 0);
    cvtw_kernel<<<nb_cvtw, 256, 0, sM>>>(gcn1w, gcn2w, 0);
    cudaEventRecord(evCvt[0], sM);
    cvt_kernel<<<nb_cvt, 256, 0, sM>>>(x_b, n_quads, 1);
    cvtw_kernel<<<nb_cvtw, 256, 0, sM>>>(gcn1w, gcn2w, 1);
    cudaEventRecord(evCvt[1], sM);
    meta_kernel<<<1, 256, 0, sM>>>(meta_a, meta_b, fc1w, fc1b, fc2w, fc2b);

    for (int g = 0; g < 2; g++) {
        const int* src = g ? ei_b : ei_a;
        const int* dst = src + E;
        cudaStream_t st = g ? sB : (cudaStream_t)0;

        count_kernel<<<nb_edges, 256, 0, st>>>(dst, E, g);
        scan_sum_kernel<<<nb_scan, 256, 0, st>>>(N, g);
        scan_top_kernel<<<1, 64, 0, st>>>(nb_scan, g);
        scan_out_kernel<<<nb_scan, 256, 0, st>>>(N, g);
        fill_kernel<<<nb_edges, 256, 0, st>>>(src, dst, E, g);

        cudaStreamWaitEvent(st, evCvt[g], 0);

        agg_kernel<<<nb_agg, 256, 0, st>>>(0, N, g);
        gemm_kernel<<<nb_gemm, 256, GEMM_SMEM, st>>>(gcn1b, N, g, 0);
        agg_kernel<<<nb_agg, 256, 0, st>>>(1, N, g);
        gemm_kernel<<<nb_gemm, 256, GEMM_SMEM, st>>>(gcn2b, N, g, 1);
        agg_kernel<<<nb_agg, 256, 0, st>>>(1, N, g);
        gemm_kernel<<<nb_gemm, 256, GEMM_SMEM, st>>>(gcn2b, N, g, 1);

        pool_partial_kernel<<<PBLK, F, 0, st>>>(N, g);
    }

    cudaEventRecord(evB, sB);
    cudaEventRecord(evM, sM);
    cudaStreamWaitEvent(0, evB, 0);
    cudaStreamWaitEvent(0, evM, 0);

    tail_kernel<<<1, 256>>>(fccw, fccb, fcc2w, fcc2b, outw, outb,
                            invN, (float*)d_out);
}